// round 1
// baseline (speedup 1.0000x reference)
#include <cuda_runtime.h>
#include <math.h>

#define BB 128
#define AA 512
#define RR 512
#define OUTN 10000
#define BR (BB*RR)
#define BA (BB*AA)

typedef unsigned long long ull;

// ---------------- scratch (device globals; no allocations) ----------------
__device__ float g_v1[(size_t)BB*AA*AA];      // 134 MB: v1 = att @ a2a1_w^T + a2a1_b
__device__ float g_spart[2*BB*8*AA];          // per-ktile score partials (2 sets)
__device__ float g_w0[BA];
__device__ float g_w1[BA];
__device__ float g_hh[2*BA];
__device__ float g_scores[BA];
__device__ float g_attres[2*BR];
__device__ float g_sums[BB*4096];
__device__ float g_nexth[BR];
__device__ float g_xt[BR];
__device__ float g_logits[BB*OUTN];

// ---------------- f32x2 packed FMA helpers (sm_100+) ----------------
__device__ __forceinline__ ull pack2(float x, float y){
    ull r; asm("mov.b64 %0, {%1, %2};" : "=l"(r) : "f"(x), "f"(y)); return r;
}
__device__ __forceinline__ ull fma2(ull a, ull b, ull c){
    ull d; asm("fma.rn.f32x2 %0, %1, %2, %3;" : "=l"(d) : "l"(a), "l"(b), "l"(c)); return d;
}
__device__ __forceinline__ float2 unpack2(ull v){
    float2 f; asm("mov.b64 {%0, %1}, %2;" : "=f"(f.x), "=f"(f.y) : "l"(v)); return f;
}

// =====================================================================
// Fused kernel: for each (b, a-tile, k-tile):
//   v0 = att[b] @ a2a_w^T   -> tanh(v0+ba0+hh{0,1}) . wd  -> score partials
//   v1 = att[b] @ a2a1_w^T + ba1 -> materialized to g_v1
// 64x64 tiles, BK=16, 256 threads, 4x4 micro-tile, f32x2 accumulators.
// =====================================================================
__global__ __launch_bounds__(256)
void fused_v_kernel(const float* __restrict__ att,
                    const float* __restrict__ Wa0, const float* __restrict__ ba0,
                    const float* __restrict__ Wa1, const float* __restrict__ ba1,
                    const float* __restrict__ wd0,
                    const float* __restrict__ hh0, const float* __restrict__ hh1,
                    float* __restrict__ v1out,
                    float* __restrict__ spart0, float* __restrict__ spart1)
{
    __shared__ float As[16][64];
    __shared__ float W0s[16][64];
    __shared__ float W1s[16][64];
    int tid = threadIdx.x;
    int kt = blockIdx.x, at = blockIdx.y, b = blockIdx.z;
    int aBase = at*64, kBase = kt*64;
    int tr = tid>>4, tc = tid&15;
    int lrow = tid>>2, lq = (tid&3)<<2;

    ull acc0[4][2], acc1[4][2];
    #pragma unroll
    for (int i=0;i<4;i++){ acc0[i][0]=0ull; acc0[i][1]=0ull; acc1[i][0]=0ull; acc1[i][1]=0ull; }

    const float* attp = att + ((size_t)b*AA + aBase + lrow)*RR + lq;
    const float* w0p_ = Wa0 + (size_t)(kBase + lrow)*RR + lq;
    const float* w1p_ = Wa1 + (size_t)(kBase + lrow)*RR + lq;

    for (int r0=0; r0<RR; r0+=16){
        float4 av  = *(const float4*)(attp + r0);
        float4 w0v = *(const float4*)(w0p_ + r0);
        float4 w1v = *(const float4*)(w1p_ + r0);
        __syncthreads();
        As [lq+0][lrow]=av.x;  As [lq+1][lrow]=av.y;  As [lq+2][lrow]=av.z;  As [lq+3][lrow]=av.w;
        W0s[lq+0][lrow]=w0v.x; W0s[lq+1][lrow]=w0v.y; W0s[lq+2][lrow]=w0v.z; W0s[lq+3][lrow]=w0v.w;
        W1s[lq+0][lrow]=w1v.x; W1s[lq+1][lrow]=w1v.y; W1s[lq+2][lrow]=w1v.z; W1s[lq+3][lrow]=w1v.w;
        __syncthreads();
        #pragma unroll
        for (int kk=0;kk<16;kk++){
            ull xa2[4];
            #pragma unroll
            for (int i=0;i<4;i++){ float xv = As[kk][tr*4+i]; xa2[i]=pack2(xv,xv); }
            ull wq0[2], wq1[2];
            wq0[0] = *(const ull*)&W0s[kk][tc*4];
            wq0[1] = *(const ull*)&W0s[kk][tc*4+2];
            wq1[0] = *(const ull*)&W1s[kk][tc*4];
            wq1[1] = *(const ull*)&W1s[kk][tc*4+2];
            #pragma unroll
            for (int i=0;i<4;i++){
                acc0[i][0]=fma2(xa2[i], wq0[0], acc0[i][0]);
                acc0[i][1]=fma2(xa2[i], wq0[1], acc0[i][1]);
                acc1[i][0]=fma2(xa2[i], wq1[0], acc1[i][0]);
                acc1[i][1]=fma2(xa2[i], wq1[1], acc1[i][1]);
            }
        }
    }

    int kcol = kBase + tc*4;
    float bb0[4], bb1[4], wdv[4];
    #pragma unroll
    for (int j=0;j<4;j++){ bb0[j]=ba0[kcol+j]; bb1[j]=ba1[kcol+j]; wdv[j]=wd0[kcol+j]; }

    #pragma unroll
    for (int i=0;i<4;i++){
        int a = aBase + tr*4 + i;
        float h0 = hh0[(size_t)b*AA + a];
        float h1 = hh1[(size_t)b*AA + a];
        float2 v00 = unpack2(acc0[i][0]);
        float2 v01 = unpack2(acc0[i][1]);
        float v0[4] = { v00.x+bb0[0], v00.y+bb0[1], v01.x+bb0[2], v01.y+bb0[3] };
        float p0=0.f, p1=0.f;
        #pragma unroll
        for (int j=0;j<4;j++){
            p0 += tanhf(v0[j]+h0)*wdv[j];
            p1 += tanhf(v0[j]+h1)*wdv[j];
        }
        float2 u0 = unpack2(acc1[i][0]);
        float2 u1 = unpack2(acc1[i][1]);
        float4 st = make_float4(u0.x+bb1[0], u0.y+bb1[1], u1.x+bb1[2], u1.y+bb1[3]);
        *(float4*)(v1out + ((size_t)b*AA + a)*AA + kcol) = st;
        // reduce partials across the 16 k-columns (16-lane segments)
        #pragma unroll
        for (int off=8; off; off>>=1){
            p0 += __shfl_down_sync(0xffffffffu, p0, off, 16);
            p1 += __shfl_down_sync(0xffffffffu, p1, off, 16);
        }
        if (tc==0){
            size_t idx = ((size_t)b*8 + kt)*AA + a;
            spart0[idx]=p0;
            spart1[idx]=p1;
        }
    }
}

// ---------------- generic C = X @ W^T (+bias)(+=C), M multiple of 64 ----------------
__global__ __launch_bounds__(256)
void gemm_kernel(const float* __restrict__ X, const float* __restrict__ W,
                 const float* __restrict__ bias, float* __restrict__ C,
                 int N, int K, int accum)
{
    __shared__ float Xs[16][64];
    __shared__ float Ws[16][64];
    int tid = threadIdx.x;
    int n0 = blockIdx.x*64, m0 = blockIdx.y*64;
    int tr = tid>>4, tc = tid&15;
    int lrow = tid>>2, lq = (tid&3)<<2;
    float acc[4][4];
    #pragma unroll
    for (int i=0;i<4;i++)
        #pragma unroll
        for (int j=0;j<4;j++) acc[i][j]=0.f;
    const float* xp = X + (size_t)(m0+lrow)*K + lq;
    int wr = n0 + lrow;
    const float* wp = W + (size_t)wr*K + lq;
    bool wok = wr < N;
    for (int k0=0;k0<K;k0+=16){
        float4 xv = *(const float4*)(xp + k0);
        float4 wv = make_float4(0.f,0.f,0.f,0.f);
        if (wok) wv = *(const float4*)(wp + k0);
        __syncthreads();
        Xs[lq+0][lrow]=xv.x; Xs[lq+1][lrow]=xv.y; Xs[lq+2][lrow]=xv.z; Xs[lq+3][lrow]=xv.w;
        Ws[lq+0][lrow]=wv.x; Ws[lq+1][lrow]=wv.y; Ws[lq+2][lrow]=wv.z; Ws[lq+3][lrow]=wv.w;
        __syncthreads();
        #pragma unroll
        for (int kk=0;kk<16;kk++){
            float xa[4], wb[4];
            #pragma unroll
            for (int i=0;i<4;i++) xa[i]=Xs[kk][tr*4+i];
            #pragma unroll
            for (int j=0;j<4;j++) wb[j]=Ws[kk][tc*4+j];
            #pragma unroll
            for (int i=0;i<4;i++)
                #pragma unroll
                for (int j=0;j<4;j++)
                    acc[i][j] = fmaf(xa[i], wb[j], acc[i][j]);
        }
    }
    #pragma unroll
    for (int i=0;i<4;i++){
        int m = m0 + tr*4 + i;
        #pragma unroll
        for (int j=0;j<4;j++){
            int n = n0 + tc*4 + j;
            if (n < N){
                float v = acc[i][j] + (bias ? bias[n] : 0.f);
                size_t ci = (size_t)m*N + n;
                if (accum) v += C[ci];
                C[ci] = v;
            }
        }
    }
}

// ---------------- softmax over a (A=512), summing nparts partials ----------------
__global__ void softmax512_kernel(const float* __restrict__ in, float* __restrict__ out, int nparts)
{
    __shared__ float sm[8];
    int b = blockIdx.x, t = threadIdx.x;
    float v0=0.f, v1=0.f;
    for (int p=0;p<nparts;p++){
        const float* ip = in + ((size_t)b*nparts + p)*AA;
        v0 += ip[t]; v1 += ip[t+256];
    }
    float m = fmaxf(v0,v1);
    for (int o=16;o;o>>=1) m = fmaxf(m, __shfl_xor_sync(0xffffffffu,m,o));
    if ((t&31)==0) sm[t>>5]=m;
    __syncthreads();
    float M = sm[0];
    #pragma unroll
    for (int i=1;i<8;i++) M = fmaxf(M, sm[i]);
    __syncthreads();
    float e0=expf(v0-M), e1=expf(v1-M);
    float s = e0+e1;
    for (int o=16;o;o>>=1) s += __shfl_xor_sync(0xffffffffu,s,o);
    if ((t&31)==0) sm[t>>5]=s;
    __syncthreads();
    float S=0.f;
    #pragma unroll
    for (int i=0;i<8;i++) S += sm[i];
    float inv = 1.f/S;
    out[(size_t)b*AA + t]     = e0*inv;
    out[(size_t)b*AA + t+256] = e1*inv;
}

// ---------------- score scan over materialized v1 ----------------
__global__ void v1_scores_kernel(const float* __restrict__ v1, const float* __restrict__ hh,
                                 const float* __restrict__ wd, float* __restrict__ scores)
{
    __shared__ float sm[4];
    int a = blockIdx.x, b = blockIdx.y, t = threadIdx.x; // 128 threads
    float h = hh[(size_t)b*AA + a];
    float4 v = ((const float4*)(v1 + ((size_t)b*AA + a)*AA))[t];
    float4 w = ((const float4*)wd)[t];
    float s = tanhf(v.x+h)*w.x + tanhf(v.y+h)*w.y + tanhf(v.z+h)*w.z + tanhf(v.w+h)*w.w;
    for (int o=16;o;o>>=1) s += __shfl_xor_sync(0xffffffffu,s,o);
    if ((t&31)==0) sm[t>>5]=s;
    __syncthreads();
    if (t==0) scores[(size_t)b*AA + a] = sm[0]+sm[1]+sm[2]+sm[3];
}

// ---------------- att_res = sum_a w[b,a]*att[b,a,r] (+add) ----------------
template<bool DUAL, bool ADD>
__global__ void attres_kernel(const float* __restrict__ att,
                              const float* __restrict__ w0, const float* __restrict__ w1,
                              const float* __restrict__ add0,
                              float* __restrict__ out0, float* __restrict__ out1)
{
    __shared__ float sw0[AA];
    __shared__ float sw1[AA];
    int b = blockIdx.y;
    int r = blockIdx.x*256 + threadIdx.x;
    for (int a=threadIdx.x; a<AA; a+=256){
        sw0[a]=w0[(size_t)b*AA+a];
        if (DUAL) sw1[a]=w1[(size_t)b*AA+a];
    }
    __syncthreads();
    float acc0=0.f, acc1=0.f;
    const float* ap = att + (size_t)b*AA*RR + r;
    #pragma unroll 8
    for (int a=0;a<AA;a++){
        float av = ap[(size_t)a*RR];
        acc0 = fmaf(sw0[a], av, acc0);
        if (DUAL) acc1 = fmaf(sw1[a], av, acc1);
    }
    if (ADD) acc0 += add0[(size_t)b*RR + r];
    out0[(size_t)b*RR + r] = acc0;
    if (DUAL) out1[(size_t)b*RR + r] = acc1;
}

// ---------------- LSTM pointwise: gates, mean over P=2 ----------------
__global__ void lstm_pw_kernel(const float* __restrict__ sums, const float* __restrict__ prev_c,
                               float* __restrict__ next_c, float* __restrict__ next_h)
{
    int idx = blockIdx.x*256 + threadIdx.x;   // 0..BR-1
    int b = idx >> 9, r = idx & 511;
    const float* s = sums + (size_t)b*4096;
    float pc = prev_c[idx];
    float cs=0.f, hs=0.f;
    #pragma unroll
    for (int p=0;p<2;p++){
        int base = p*2048 + r;
        float ig = 1.f/(1.f+expf(-s[base]));
        float fg = 1.f/(1.f+expf(-s[base+512]));
        float og = 1.f/(1.f+expf(-s[base+1024]));
        float tt = tanhf(s[base+1536]);
        float c  = fg*pc + ig*tt;
        cs += c; hs += og*tanhf(c);
    }
    next_c[idx] = cs*0.5f;
    next_h[idx] = hs*0.5f;
}

__global__ void add_kernel(const float* __restrict__ a, const float* __restrict__ b2,
                           float* __restrict__ c, int n)
{
    int i = blockIdx.x*256 + threadIdx.x;
    if (i<n) c[i]=a[i]+b2[i];
}

// ---------------- log_softmax over OUTN=10000 ----------------
__global__ void logsoftmax_kernel(const float* __restrict__ logits, float* __restrict__ out)
{
    __shared__ float sm[8];
    int b = blockIdx.x, t = threadIdx.x;
    const float* x = logits + (size_t)b*OUTN;
    float m = -3.4e38f;
    for (int i=t;i<OUTN;i+=256) m = fmaxf(m, x[i]);
    for (int o=16;o;o>>=1) m = fmaxf(m, __shfl_xor_sync(0xffffffffu,m,o));
    if ((t&31)==0) sm[t>>5]=m;
    __syncthreads();
    float M = sm[0];
    #pragma unroll
    for (int i=1;i<8;i++) M = fmaxf(M, sm[i]);
    __syncthreads();
    float s=0.f;
    for (int i=t;i<OUTN;i+=256) s += expf(x[i]-M);
    for (int o=16;o;o>>=1) s += __shfl_xor_sync(0xffffffffu,s,o);
    if ((t&31)==0) sm[t>>5]=s;
    __syncthreads();
    float S=0.f;
    #pragma unroll
    for (int i=0;i<8;i++) S += sm[i];
    float L = M + logf(S);
    for (int i=t;i<OUTN;i+=256) out[(size_t)b*OUTN+i] = x[i]-L;
}

// =====================================================================
extern "C" void kernel_launch(void* const* d_in, const int* in_sizes, int n_in,
                              void* d_out, int out_size)
{
    const float* x      = (const float*)d_in[0];
    const float* att    = (const float*)d_in[1];
    const float* inputs = (const float*)d_in[2];
    const float* a2a_w  = (const float*)d_in[3];
    const float* a2a_b  = (const float*)d_in[4];
    const float* h2a_w  = (const float*)d_in[5];
    const float* h2a_b  = (const float*)d_in[6];
    const float* d2d_w  = (const float*)d_in[7];
    /* d_in[8] = d2d_b : dropped (softmax shift invariance) */
    const float* a2a1_w = (const float*)d_in[9];
    const float* a2a1_b = (const float*)d_in[10];
    const float* h2a1_w = (const float*)d_in[11];
    const float* h2a1_b = (const float*)d_in[12];
    const float* d2d1_w = (const float*)d_in[13];
    /* d_in[14] = d2d1_b : dropped */
    const float* i2h_w  = (const float*)d_in[15];
    const float* i2h_b  = (const float*)d_in[16];
    const float* h2h_w  = (const float*)d_in[17];
    const float* h2h_b  = (const float*)d_in[18];
    const float* a2h_w  = (const float*)d_in[19];
    const float* a2h_b  = (const float*)d_in[20];
    const float* proj_w = (const float*)d_in[21];
    const float* proj_b = (const float*)d_in[22];
    float* out = (float*)d_out;

    float *v1p, *spart, *w0p, *w1p, *hhp, *scoresp, *attresp, *sumsp, *nexthp, *xtp, *logitsp;
    cudaGetSymbolAddress((void**)&v1p,     g_v1);
    cudaGetSymbolAddress((void**)&spart,   g_spart);
    cudaGetSymbolAddress((void**)&w0p,     g_w0);
    cudaGetSymbolAddress((void**)&w1p,     g_w1);
    cudaGetSymbolAddress((void**)&hhp,     g_hh);
    cudaGetSymbolAddress((void**)&scoresp, g_scores);
    cudaGetSymbolAddress((void**)&attresp, g_attres);
    cudaGetSymbolAddress((void**)&sumsp,   g_sums);
    cudaGetSymbolAddress((void**)&nexthp,  g_nexth);
    cudaGetSymbolAddress((void**)&xtp,     g_xt);
    cudaGetSymbolAddress((void**)&logitsp, g_logits);

    const float* prev_c0 = inputs;
    const float* prev_h0 = inputs + 1*BR;
    const float* prev_c1 = inputs + 2*BR;
    const float* prev_h1 = inputs + 3*BR;

    dim3 g512(8,2), g4096(64,2), g10000((OUTN+63)/64, 2);
    const size_t LW = 2097152;  // per-layer weight stride (P*4R*IN)
    const int    LB = 4096;     // per-layer bias stride

    // hh for both prev-attends (set0 weights) — known upfront
    gemm_kernel<<<g512,256>>>(prev_h0, h2a_w, h2a_b, hhp,    AA, RR, 0);
    gemm_kernel<<<g512,256>>>(prev_h1, h2a_w, h2a_b, hhp+BA, AA, RR, 0);

    // fused: v0 -> scores(prev0, prev1);  v1 -> materialize
    fused_v_kernel<<<dim3(8,8,BB),256>>>(att, a2a_w, a2a_b, a2a1_w, a2a1_b, d2d_w,
                                         hhp, hhp+BA, v1p, spart, spart + (size_t)BB*8*AA);

    softmax512_kernel<<<BB,256>>>(spart,                 w0p, 8);
    softmax512_kernel<<<BB,256>>>(spart + (size_t)BB*8*AA, w1p, 8);

    // both prev att_res in one att pass
    attres_kernel<true,false><<<dim3(2,BB),256>>>(att, w0p, w1p, nullptr, attresp, attresp+BR);

    // ---- layer 0 ----
    gemm_kernel<<<g4096,256>>>(x,       i2h_w, i2h_b, sumsp, 4096, RR, 0);
    gemm_kernel<<<g4096,256>>>(prev_h0, h2h_w, h2h_b, sumsp, 4096, RR, 1);
    gemm_kernel<<<g4096,256>>>(attresp, a2h_w, a2h_b, sumsp, 4096, RR, 1);
    lstm_pw_kernel<<<BR/256,256>>>(sumsp, prev_c0, out + 0, nexthp);

    gemm_kernel<<<g512,256>>>(nexthp, h2a1_w, h2a1_b, hhp, AA, RR, 0);
    v1_scores_kernel<<<dim3(AA,BB),128>>>(v1p, hhp, d2d1_w, scoresp);
    softmax512_kernel<<<BB,256>>>(scoresp, w0p, 1);
    attres_kernel<false,true><<<dim3(2,BB),256>>>(att, w0p, nullptr, nexthp, out + BR, nullptr); // top_h0
    add_kernel<<<BR/256,256>>>(x, out + BR, xtp, BR);   // xt = x + top_h0

    // ---- layer 1 ----
    gemm_kernel<<<g4096,256>>>(xtp,        i2h_w + LW, i2h_b + LB, sumsp, 4096, RR, 0);
    gemm_kernel<<<g4096,256>>>(prev_h1,    h2h_w + LW, h2h_b + LB, sumsp, 4096, RR, 1);
    gemm_kernel<<<g4096,256>>>(attresp+BR, a2h_w + LW, a2h_b + LB, sumsp, 4096, RR, 1);
    lstm_pw_kernel<<<BR/256,256>>>(sumsp, prev_c1, out + 2*BR, nexthp);

    gemm_kernel<<<g512,256>>>(nexthp, h2a1_w, h2a1_b, hhp, AA, RR, 0);
    v1_scores_kernel<<<dim3(AA,BB),128>>>(v1p, hhp, d2d1_w, scoresp);
    softmax512_kernel<<<BB,256>>>(scoresp, w0p, 1);
    attres_kernel<false,true><<<dim3(2,BB),256>>>(att, w0p, nullptr, nexthp, out + 3*BR, nullptr); // top_h1

    // ---- projection + log_softmax ----
    gemm_kernel<<<g10000,256>>>(out + 3*BR, proj_w, proj_b, logitsp, OUTN, RR, 0);
    logsoftmax_kernel<<<BB,256>>>(logitsp, out + 4*BR);
}

// round 3
// speedup vs baseline: 1.9082x; 1.9082x over previous
#include <cuda_runtime.h>
#include <cuda_bf16.h>
#include <math.h>
#include <cstdint>

#define BB 128
#define AA 512
#define RR 512
#define OUTN 10000
#define BR (BB*RR)
#define BA (BB*AA)

// HMMA GEMM tiling
#define MT 128
#define NT 128
#define KSTAGE 64
#define NSTAGES 8
#define STAGE_BYTES 65536   // Ahi 16K + Alo 16K + Bhi 16K + Blo 16K

// ---------------- scratch (device globals; no allocations) ----------------
__device__ float g_v1[(size_t)BB*AA*AA];      // 134 MB: v1 = att @ a2a1_w^T + a2a1_b
__device__ float g_spart[2*8*BA];             // 8 score partials per set
__device__ float g_w0[BA];
__device__ float g_w1[BA];
__device__ float g_hh[2*BA];
__device__ float g_scores[BA];
__device__ float g_attres[2*BR];
__device__ float g_sums[BB*4096];
__device__ float g_nexth[BR];
__device__ float g_xt[BR];
__device__ float g_logits[BB*OUTN];
// split-precision bf16 operands
__device__ __nv_bfloat16 g_att_hi[(size_t)BB*AA*RR];
__device__ __nv_bfloat16 g_att_lo[(size_t)BB*AA*RR];
__device__ __nv_bfloat16 g_w0_hi[AA*RR];
__device__ __nv_bfloat16 g_w0_lo[AA*RR];
__device__ __nv_bfloat16 g_w1_hi[AA*RR];
__device__ __nv_bfloat16 g_w1_lo[AA*RR];

// ---------------- PTX helpers ----------------
__device__ __forceinline__ uint32_t smem_u32(const void* p){
    uint32_t a;
    asm("{ .reg .u64 t; cvta.to.shared.u64 t, %1; cvt.u32.u64 %0, t; }" : "=r"(a) : "l"(p));
    return a;
}
__device__ __forceinline__ void cp16(uint32_t dst, const void* src){
    asm volatile("cp.async.cg.shared.global [%0], [%1], 16;\n" :: "r"(dst), "l"(src));
}
#define CP_COMMIT()  asm volatile("cp.async.commit_group;\n" ::: "memory")
#define CP_WAIT0()   asm volatile("cp.async.wait_group 0;\n" ::: "memory")
#define CP_WAIT1()   asm volatile("cp.async.wait_group 1;\n" ::: "memory")

#define SWZ(off) ((off) ^ (((off) >> 3) & 0x70))

__device__ __forceinline__ uint32_t lds_u32(uint32_t addr){
    uint32_t v; asm volatile("ld.shared.b32 %0, [%1];" : "=r"(v) : "r"(addr)); return v;
}

// mma.sync m16n8k16 bf16 row.col, fp32 accumulate (in place)
__device__ __forceinline__ void mma16816(float* c, const uint32_t* a, const uint32_t* b){
    asm volatile(
        "mma.sync.aligned.m16n8k16.row.col.f32.bf16.bf16.f32 "
        "{%0,%1,%2,%3}, {%4,%5,%6,%7}, {%8,%9}, {%0,%1,%2,%3};"
        : "+f"(c[0]), "+f"(c[1]), "+f"(c[2]), "+f"(c[3])
        : "r"(a[0]), "r"(a[1]), "r"(a[2]), "r"(a[3]), "r"(b[0]), "r"(b[1]));
}

// ---------------- split fp32 -> bf16 hi/lo ----------------
__global__ void split_bf16_kernel(const float* __restrict__ in,
                                  __nv_bfloat16* __restrict__ hi,
                                  __nv_bfloat16* __restrict__ lo, size_t n4)
{
    size_t i = (size_t)blockIdx.x*blockDim.x + threadIdx.x;
    if (i >= n4) return;
    float4 x = ((const float4*)in)[i];
    __nv_bfloat16 h[4], l[4];
    float xv[4] = {x.x, x.y, x.z, x.w};
    #pragma unroll
    for (int j=0;j<4;j++){
        h[j] = __float2bfloat16(xv[j]);
        l[j] = __float2bfloat16(xv[j] - __bfloat162float(h[j]));
    }
    ((uint2*)hi)[i] = *(uint2*)h;
    ((uint2*)lo)[i] = *(uint2*)l;
}

// =====================================================================
// HMMA split-bf16 GEMM: C[m,n] = sum_r ATT[m,r] * W[n,r]
// grid.x = (ntile<<1)|set  (8), grid.y = mtile (512).
// set0: fused tanh+wd score partials (8 parts); set1: v1 materialized (+bias).
// =====================================================================
__global__ __launch_bounds__(256, 1)
void hmma_gemm_kernel(const __nv_bfloat16* __restrict__ Ahi, const __nv_bfloat16* __restrict__ Alo,
                      const __nv_bfloat16* __restrict__ W0hi, const __nv_bfloat16* __restrict__ W0lo,
                      const __nv_bfloat16* __restrict__ W1hi, const __nv_bfloat16* __restrict__ W1lo,
                      const float* __restrict__ ba0, const float* __restrict__ ba1,
                      const float* __restrict__ wd0,
                      const float* __restrict__ hh0, const float* __restrict__ hh1,
                      float* __restrict__ v1out,
                      float* __restrict__ sp0, float* __restrict__ sp1)
{
    extern __shared__ char dsm[];
    const int tid  = threadIdx.x;
    const int wid  = tid >> 5;
    const int lane = tid & 31;
    const int grp  = lane >> 2;
    const int tid4 = lane & 3;
    const int set  = blockIdx.x & 1;
    const int nt4  = blockIdx.x >> 1;          // 0..3
    const int mBase = blockIdx.y * MT;
    const int nBase4 = nt4 * NT;
    const int wm = wid >> 1;                   // 0..3 (M)
    const int wn = wid & 1;                    // 0..1 (N)

    const __nv_bfloat16* Whi = set ? W1hi : W0hi;
    const __nv_bfloat16* Wlo = set ? W1lo : W0lo;
    const float* bias = set ? ba1 : ba0;

    const uint32_t sbase = smem_u32(dsm);

    float acc[2][8][4];
    #pragma unroll
    for (int mt=0;mt<2;mt++)
        #pragma unroll
        for (int nt=0;nt<8;nt++)
            #pragma unroll
            for (int q=0;q<4;q++) acc[mt][nt][q]=0.f;

    // stage loader: 16B cp.async chunks into SW128-swizzled smem
    auto load_stage = [&](int s){
        const uint32_t base = sbase + (s & 1) * STAGE_BYTES;
        const int kOff = s * KSTAGE;
        #pragma unroll
        for (int i = 0; i < 8; i++){                 // A: 2048 chunks
            int idx = tid + i * 256;
            int half = idx >> 10;
            int r = (idx >> 3) & 127;
            int ch = idx & 7;
            const __nv_bfloat16* src = (half ? Alo : Ahi) + (size_t)(mBase + r) * RR + kOff + ch * 8;
            cp16(base + half * 16384 + SWZ(r * 128 + ch * 16), src);
        }
        #pragma unroll
        for (int i = 0; i < 8; i++){                 // B: 2048 chunks
            int idx = tid + i * 256;
            int half = idx >> 10;
            int r = (idx >> 3) & 127;
            int ch = idx & 7;
            const __nv_bfloat16* src = (half ? Wlo : Whi) + (size_t)(nBase4 + r) * RR + kOff + ch * 8;
            cp16(base + 32768 + half * 16384 + SWZ(r * 128 + ch * 16), src);
        }
        CP_COMMIT();
    };

    load_stage(0);

    for (int s = 0; s < NSTAGES; s++){
        if (s + 1 < NSTAGES){ load_stage(s + 1); CP_WAIT1(); }
        else                 { CP_WAIT0(); }
        __syncthreads();

        const uint32_t sA = sbase + (s & 1) * STAGE_BYTES;
        const uint32_t sB = sA + 32768;
        #pragma unroll
        for (int k16 = 0; k16 < 4; k16++){
            const int kc = k16 * 32 + tid4 * 4;   // byte offset in 128B row
            uint32_t aH[2][4], aL[2][4];
            #pragma unroll
            for (int mt = 0; mt < 2; mt++){
                int r0 = (wm*32 + mt*16 + grp) * 128 + kc;
                int r1 = r0 + 8*128;
                aH[mt][0] = lds_u32(sA + SWZ(r0));
                aH[mt][1] = lds_u32(sA + SWZ(r1));
                aH[mt][2] = lds_u32(sA + SWZ(r0 + 16));
                aH[mt][3] = lds_u32(sA + SWZ(r1 + 16));
                aL[mt][0] = lds_u32(sA + 16384 + SWZ(r0));
                aL[mt][1] = lds_u32(sA + 16384 + SWZ(r1));
                aL[mt][2] = lds_u32(sA + 16384 + SWZ(r0 + 16));
                aL[mt][3] = lds_u32(sA + 16384 + SWZ(r1 + 16));
            }
            #pragma unroll
            for (int nt = 0; nt < 8; nt++){
                int rb = (wn*64 + nt*8 + grp) * 128 + kc;
                uint32_t bH[2], bL[2];
                bH[0] = lds_u32(sB + SWZ(rb));
                bH[1] = lds_u32(sB + SWZ(rb + 16));
                bL[0] = lds_u32(sB + 16384 + SWZ(rb));
                bL[1] = lds_u32(sB + 16384 + SWZ(rb + 16));
                #pragma unroll
                for (int mt = 0; mt < 2; mt++){
                    mma16816(acc[mt][nt], aH[mt], bH);
                    mma16816(acc[mt][nt], aH[mt], bL);
                    mma16816(acc[mt][nt], aL[mt], bH);
                }
            }
        }
        __syncthreads();
    }

    // ---- epilogue ----
    if (set == 1){
        #pragma unroll
        for (int mt = 0; mt < 2; mt++){
            #pragma unroll
            for (int rh = 0; rh < 2; rh++){
                int m = mBase + wm*32 + mt*16 + rh*8 + grp;
                float* dst = v1out + (size_t)m * AA;
                #pragma unroll
                for (int nt = 0; nt < 8; nt++){
                    int n0 = nBase4 + wn*64 + nt*8 + tid4*2;
                    float2 v2;
                    v2.x = acc[mt][nt][rh*2+0] + bias[n0];
                    v2.y = acc[mt][nt][rh*2+1] + bias[n0+1];
                    *(float2*)(dst + n0) = v2;
                }
            }
        }
    } else {
        const int part = nt4*2 + wn;   // 0..7
        #pragma unroll
        for (int mt = 0; mt < 2; mt++){
            #pragma unroll
            for (int rh = 0; rh < 2; rh++){
                int m = mBase + wm*32 + mt*16 + rh*8 + grp;
                float h0 = hh0[m], h1 = hh1[m];
                float p0 = 0.f, p1 = 0.f;
                #pragma unroll
                for (int nt = 0; nt < 8; nt++){
                    int n0 = nBase4 + wn*64 + nt*8 + tid4*2;
                    float v0 = acc[mt][nt][rh*2+0] + bias[n0];
                    float v1v = acc[mt][nt][rh*2+1] + bias[n0+1];
                    float wv0 = wd0[n0], wv1 = wd0[n0+1];
                    p0 += tanhf(v0 + h0)*wv0 + tanhf(v1v + h0)*wv1;
                    p1 += tanhf(v0 + h1)*wv0 + tanhf(v1v + h1)*wv1;
                }
                p0 += __shfl_down_sync(0xffffffffu, p0, 2, 4);
                p0 += __shfl_down_sync(0xffffffffu, p0, 1, 4);
                p1 += __shfl_down_sync(0xffffffffu, p1, 2, 4);
                p1 += __shfl_down_sync(0xffffffffu, p1, 1, 4);
                if (tid4 == 0){
                    sp0[(size_t)part*BA + m] = p0;
                    sp1[(size_t)part*BA + m] = p1;
                }
            }
        }
    }
}

// ---------------- generic C = X @ W^T (+bias)(+=C), M multiple of 64 ----------------
__global__ __launch_bounds__(256)
void gemm_kernel(const float* __restrict__ X, const float* __restrict__ W,
                 const float* __restrict__ bias, float* __restrict__ C,
                 int N, int K, int accum)
{
    __shared__ float Xs[16][64];
    __shared__ float Ws[16][64];
    int tid = threadIdx.x;
    int n0 = blockIdx.x*64, m0 = blockIdx.y*64;
    int tr = tid>>4, tc = tid&15;
    int lrow = tid>>2, lq = (tid&3)<<2;
    float acc[4][4];
    #pragma unroll
    for (int i=0;i<4;i++)
        #pragma unroll
        for (int j=0;j<4;j++) acc[i][j]=0.f;
    const float* xp = X + (size_t)(m0+lrow)*K + lq;
    int wr = n0 + lrow;
    const float* wp = W + (size_t)wr*K + lq;
    bool wok = wr < N;
    for (int k0=0;k0<K;k0+=16){
        float4 xv = *(const float4*)(xp + k0);
        float4 wv = make_float4(0.f,0.f,0.f,0.f);
        if (wok) wv = *(const float4*)(wp + k0);
        __syncthreads();
        Xs[lq+0][lrow]=xv.x; Xs[lq+1][lrow]=xv.y; Xs[lq+2][lrow]=xv.z; Xs[lq+3][lrow]=xv.w;
        Ws[lq+0][lrow]=wv.x; Ws[lq+1][lrow]=wv.y; Ws[lq+2][lrow]=wv.z; Ws[lq+3][lrow]=wv.w;
        __syncthreads();
        #pragma unroll
        for (int kk=0;kk<16;kk++){
            float xa[4], wb[4];
            #pragma unroll
            for (int i=0;i<4;i++) xa[i]=Xs[kk][tr*4+i];
            #pragma unroll
            for (int j=0;j<4;j++) wb[j]=Ws[kk][tc*4+j];
            #pragma unroll
            for (int i=0;i<4;i++)
                #pragma unroll
                for (int j=0;j<4;j++)
                    acc[i][j] = fmaf(xa[i], wb[j], acc[i][j]);
        }
    }
    #pragma unroll
    for (int i=0;i<4;i++){
        int m = m0 + tr*4 + i;
        #pragma unroll
        for (int j=0;j<4;j++){
            int n = n0 + tc*4 + j;
            if (n < N){
                float v = acc[i][j] + (bias ? bias[n] : 0.f);
                size_t ci = (size_t)m*N + n;
                if (accum) v += C[ci];
                C[ci] = v;
            }
        }
    }
}

// ---------------- softmax over a (A=512), summing nparts partials (stride BA) ----------------
__global__ void softmax512_kernel(const float* __restrict__ in, float* __restrict__ out, int nparts)
{
    __shared__ float sm[8];
    int b = blockIdx.x, t = threadIdx.x;
    float v0=0.f, v1=0.f;
    for (int p=0;p<nparts;p++){
        const float* ip = in + (size_t)p*BA + (size_t)b*AA;
        v0 += ip[t]; v1 += ip[t+256];
    }
    float m = fmaxf(v0,v1);
    for (int o=16;o;o>>=1) m = fmaxf(m, __shfl_xor_sync(0xffffffffu,m,o));
    if ((t&31)==0) sm[t>>5]=m;
    __syncthreads();
    float M = sm[0];
    #pragma unroll
    for (int i=1;i<8;i++) M = fmaxf(M, sm[i]);
    __syncthreads();
    float e0=expf(v0-M), e1=expf(v1-M);
    float s = e0+e1;
    for (int o=16;o;o>>=1) s += __shfl_xor_sync(0xffffffffu,s,o);
    if ((t&31)==0) sm[t>>5]=s;
    __syncthreads();
    float S=0.f;
    #pragma unroll
    for (int i=0;i<8;i++) S += sm[i];
    float inv = 1.f/S;
    out[(size_t)b*AA + t]     = e0*inv;
    out[(size_t)b*AA + t+256] = e1*inv;
}

// ---------------- score scan over materialized v1 ----------------
__global__ void v1_scores_kernel(const float* __restrict__ v1, const float* __restrict__ hh,
                                 const float* __restrict__ wd, float* __restrict__ scores)
{
    __shared__ float sm[4];
    int a = blockIdx.x, b = blockIdx.y, t = threadIdx.x; // 128 threads
    float h = hh[(size_t)b*AA + a];
    float4 v = ((const float4*)(v1 + ((size_t)b*AA + a)*AA))[t];
    float4 w = ((const float4*)wd)[t];
    float s = tanhf(v.x+h)*w.x + tanhf(v.y+h)*w.y + tanhf(v.z+h)*w.z + tanhf(v.w+h)*w.w;
    for (int o=16;o;o>>=1) s += __shfl_xor_sync(0xffffffffu,s,o);
    if ((t&31)==0) sm[t>>5]=s;
    __syncthreads();
    if (t==0) scores[(size_t)b*AA + a] = sm[0]+sm[1]+sm[2]+sm[3];
}

// ---------------- att_res = sum_a w[b,a]*att[b,a,r] (+add) ----------------
template<bool DUAL, bool ADD>
__global__ void attres_kernel(const float* __restrict__ att,
                              const float* __restrict__ w0, const float* __restrict__ w1,
                              const float* __restrict__ add0,
                              float* __restrict__ out0, float* __restrict__ out1)
{
    __shared__ float sw0[AA];
    __shared__ float sw1[AA];
    int b = blockIdx.y;
    int r = blockIdx.x*256 + threadIdx.x;
    for (int a=threadIdx.x; a<AA; a+=256){
        sw0[a]=w0[(size_t)b*AA+a];
        if (DUAL) sw1[a]=w1[(size_t)b*AA+a];
    }
    __syncthreads();
    float acc0=0.f, acc1=0.f;
    const float* ap = att + (size_t)b*AA*RR + r;
    #pragma unroll 8
    for (int a=0;a<AA;a++){
        float av = ap[(size_t)a*RR];
        acc0 = fmaf(sw0[a], av, acc0);
        if (DUAL) acc1 = fmaf(sw1[a], av, acc1);
    }
    if (ADD) acc0 += add0[(size_t)b*RR + r];
    out0[(size_t)b*RR + r] = acc0;
    if (DUAL) out1[(size_t)b*RR + r] = acc1;
}

// ---------------- LSTM pointwise: gates, mean over P=2 ----------------
__global__ void lstm_pw_kernel(const float* __restrict__ sums, const float* __restrict__ prev_c,
                               float* __restrict__ next_c, float* __restrict__ next_h)
{
    int idx = blockIdx.x*256 + threadIdx.x;   // 0..BR-1
    int b = idx >> 9, r = idx & 511;
    const float* s = sums + (size_t)b*4096;
    float pc = prev_c[idx];
    float cs=0.f, hs=0.f;
    #pragma unroll
    for (int p=0;p<2;p++){
        int base = p*2048 + r;
        float ig = 1.f/(1.f+expf(-s[base]));
        float fg = 1.f/(1.f+expf(-s[base+512]));
        float og = 1.f/(1.f+expf(-s[base+1024]));
        float tt = tanhf(s[base+1536]);
        float c  = fg*pc + ig*tt;
        cs += c; hs += og*tanhf(c);
    }
    next_c[idx] = cs*0.5f;
    next_h[idx] = hs*0.5f;
}

__global__ void add_kernel(const float* __restrict__ a, const float* __restrict__ b2,
                           float* __restrict__ c, int n)
{
    int i = blockIdx.x*256 + threadIdx.x;
    if (i<n) c[i]=a[i]+b2[i];
}

// ---------------- log_softmax over OUTN=10000 ----------------
__global__ void logsoftmax_kernel(const float* __restrict__ logits, float* __restrict__ out)
{
    __shared__ float sm[8];
    int b = blockIdx.x, t = threadIdx.x;
    const float* x = logits + (size_t)b*OUTN;
    float m = -3.4e38f;
    for (int i=t;i<OUTN;i+=256) m = fmaxf(m, x[i]);
    for (int o=16;o;o>>=1) m = fmaxf(m, __shfl_xor_sync(0xffffffffu,m,o));
    if ((t&31)==0) sm[t>>5]=m;
    __syncthreads();
    float M = sm[0];
    #pragma unroll
    for (int i=1;i<8;i++) M = fmaxf(M, sm[i]);
    __syncthreads();
    float s=0.f;
    for (int i=t;i<OUTN;i+=256) s += expf(x[i]-M);
    for (int o=16;o;o>>=1) s += __shfl_xor_sync(0xffffffffu,s,o);
    if ((t&31)==0) sm[t>>5]=s;
    __syncthreads();
    float S=0.f;
    #pragma unroll
    for (int i=0;i<8;i++) S += sm[i];
    float L = M + logf(S);
    for (int i=t;i<OUTN;i+=256) out[(size_t)b*OUTN+i] = x[i]-L;
}

// =====================================================================
extern "C" void kernel_launch(void* const* d_in, const int* in_sizes, int n_in,
                              void* d_out, int out_size)
{
    const float* x      = (const float*)d_in[0];
    const float* att    = (const float*)d_in[1];
    const float* inputs = (const float*)d_in[2];
    const float* a2a_w  = (const float*)d_in[3];
    const float* a2a_b  = (const float*)d_in[4];
    const float* h2a_w  = (const float*)d_in[5];
    const float* h2a_b  = (const float*)d_in[6];
    const float* d2d_w  = (const float*)d_in[7];
    const float* a2a1_w = (const float*)d_in[9];
    const float* a2a1_b = (const float*)d_in[10];
    const float* h2a1_w = (const float*)d_in[11];
    const float* h2a1_b = (const float*)d_in[12];
    const float* d2d1_w = (const float*)d_in[13];
    const float* i2h_w  = (const float*)d_in[15];
    const float* i2h_b  = (const float*)d_in[16];
    const float* h2h_w  = (const float*)d_in[17];
    const float* h2h_b  = (const float*)d_in[18];
    const float* a2h_w  = (const float*)d_in[19];
    const float* a2h_b  = (const float*)d_in[20];
    const float* proj_w = (const float*)d_in[21];
    const float* proj_b = (const float*)d_in[22];
    float* out = (float*)d_out;

    float *v1p, *spart, *w0p, *w1p, *hhp, *scoresp, *attresp, *sumsp, *nexthp, *xtp, *logitsp;
    __nv_bfloat16 *ahi, *alo, *w0hi, *w0lo, *w1hi, *w1lo;
    cudaGetSymbolAddress((void**)&v1p,     g_v1);
    cudaGetSymbolAddress((void**)&spart,   g_spart);
    cudaGetSymbolAddress((void**)&w0p,     g_w0);
    cudaGetSymbolAddress((void**)&w1p,     g_w1);
    cudaGetSymbolAddress((void**)&hhp,     g_hh);
    cudaGetSymbolAddress((void**)&scoresp, g_scores);
    cudaGetSymbolAddress((void**)&attresp, g_attres);
    cudaGetSymbolAddress((void**)&sumsp,   g_sums);
    cudaGetSymbolAddress((void**)&nexthp,  g_nexth);
    cudaGetSymbolAddress((void**)&xtp,     g_xt);
    cudaGetSymbolAddress((void**)&logitsp, g_logits);
    cudaGetSymbolAddress((void**)&ahi,     g_att_hi);
    cudaGetSymbolAddress((void**)&alo,     g_att_lo);
    cudaGetSymbolAddress((void**)&w0hi,    g_w0_hi);
    cudaGetSymbolAddress((void**)&w0lo,    g_w0_lo);
    cudaGetSymbolAddress((void**)&w1hi,    g_w1_hi);
    cudaGetSymbolAddress((void**)&w1lo,    g_w1_lo);

    const float* prev_c0 = inputs;
    const float* prev_h0 = inputs + 1*BR;
    const float* prev_c1 = inputs + 2*BR;
    const float* prev_h1 = inputs + 3*BR;

    dim3 g512(8,2), g4096(64,2), g10000((OUTN+63)/64, 2);
    const size_t LW = 2097152;  // per-layer weight stride (P*4R*IN)
    const int    LB = 4096;     // per-layer bias stride
    float* sp0 = spart;
    float* sp1 = spart + (size_t)8*BA;

    cudaFuncSetAttribute(hmma_gemm_kernel, cudaFuncAttributeMaxDynamicSharedMemorySize, 2*STAGE_BYTES);

    // split fp32 -> bf16 hi/lo
    {
        size_t n4 = (size_t)BB*AA*RR/4;
        split_bf16_kernel<<<(unsigned)((n4+255)/256),256>>>(att, ahi, alo, n4);
        split_bf16_kernel<<<(AA*RR/4+255)/256,256>>>(a2a_w,  w0hi, w0lo, AA*RR/4);
        split_bf16_kernel<<<(AA*RR/4+255)/256,256>>>(a2a1_w, w1hi, w1lo, AA*RR/4);
    }

    // hh for both prev-attends (set0 weights)
    gemm_kernel<<<g512,256>>>(prev_h0, h2a_w, h2a_b, hhp,    AA, RR, 0);
    gemm_kernel<<<g512,256>>>(prev_h1, h2a_w, h2a_b, hhp+BA, AA, RR, 0);

    // tensor-core GEMMs: set0 -> fused score partials, set1 -> v1 materialized (+bias)
    hmma_gemm_kernel<<<dim3(8,512),256,2*STAGE_BYTES>>>(
        ahi, alo, w0hi, w0lo, w1hi, w1lo,
        a2a_b, a2a1_b, d2d_w, hhp, hhp+BA, v1p, sp0, sp1);

    softmax512_kernel<<<BB,256>>>(sp0, w0p, 8);
    softmax512_kernel<<<BB,256>>>(sp1, w1p, 8);

    // both prev att_res in one att pass
    attres_kernel<true,false><<<dim3(2,BB),256>>>(att, w0p, w1p, nullptr, attresp, attresp+BR);

    // ---- layer 0 ----
    gemm_kernel<<<g4096,256>>>(x,       i2h_w, i2h_b, sumsp, 4096, RR, 0);
    gemm_kernel<<<g4096,256>>>(prev_h0, h2h_w, h2h_b, sumsp, 4096, RR, 1);
    gemm_kernel<<<g4096,256>>>(attresp, a2h_w, a2h_b, sumsp, 4096, RR, 1);
    lstm_pw_kernel<<<BR/256,256>>>(sumsp, prev_c0, out + 0, nexthp);

    gemm_kernel<<<g512,256>>>(nexthp, h2a1_w, h2a1_b, hhp, AA, RR, 0);
    v1_scores_kernel<<<dim3(AA,BB),128>>>(v1p, hhp, d2d1_w, scoresp);
    softmax512_kernel<<<BB,256>>>(scoresp, w0p, 1);
    attres_kernel<false,true><<<dim3(2,BB),256>>>(att, w0p, nullptr, nexthp, out + BR, nullptr); // top_h0
    add_kernel<<<BR/256,256>>>(x, out + BR, xtp, BR);   // xt = x + top_h0

    // ---- layer 1 ----
    gemm_kernel<<<g4096,256>>>(xtp,        i2h_w + LW, i2h_b + LB, sumsp, 4096, RR, 0);
    gemm_kernel<<<g4096,256>>>(prev_h1,    h2h_w + LW, h2h_b + LB, sumsp, 4096, RR, 1);
    gemm_kernel<<<g4096,256>>>(attresp+BR, a2h_w + LW, a2h_b + LB, sumsp, 4096, RR, 1);
    lstm_pw_kernel<<<BR/256,256>>>(sumsp, prev_c1, out + 2*BR, nexthp);

    gemm_kernel<<<g512,256>>>(nexthp, h2a1_w, h2a1_b, hhp, AA, RR, 0);
    v1_scores_kernel<<<dim3(AA,BB),128>>>(v1p, hhp, d2d1_w, scoresp);
    softmax512_kernel<<<BB,256>>>(scoresp, w0p, 1);
    attres_kernel<false,true><<<dim3(2,BB),256>>>(att, w0p, nullptr, nexthp, out + 3*BR, nullptr); // top_h1

    // ---- projection + log_softmax ----
    gemm_kernel<<<g10000,256>>>(out + 3*BR, proj_w, proj_b, logitsp, OUTN, RR, 0);
    logsoftmax_kernel<<<BB,256>>>(logitsp, out + 4*BR);
}

// round 4
// speedup vs baseline: 2.5110x; 1.3159x over previous
#include <cuda_runtime.h>
#include <cuda_bf16.h>
#include <math.h>
#include <cstdint>

#define BB 128
#define AA 512
#define RR 512
#define OUTN 10000
#define BR (BB*RR)
#define BA (BB*AA)
#define LW 2097152
#define LB 4096

// big HMMA GEMM tiling
#define MT 128
#define NT 128
#define KSTAGE 64
#define NSTAGES 8
#define STAGE_BYTES 65536

// generic hgemm tiling: 128x64, stage = 48KB
#define HSTG 49152

// ---------------- scratch (device globals; no allocations) ----------------
__device__ float g_v1[(size_t)BB*AA*AA];
__device__ float g_spart[2*8*BA];
__device__ float g_w0[BA];
__device__ float g_w1[BA];
__device__ float g_hh[BA];            // h2a1 reduced
__device__ float g_hhred[2*BA];       // prev hh reduced (256x512)
__device__ float g_hhpart[4*2*BA];
__device__ float g_h2a1part[4*BA];
__device__ float g_sums4[4*BB*4096];
__device__ float g_nexth[BR];
__device__ float g_scores[BA];
__device__ float g_logits2[(size_t)2*BB*OUTN];
// bf16 split operands
__device__ __nv_bfloat16 g_att_hi[(size_t)BB*AA*RR];
__device__ __nv_bfloat16 g_att_lo[(size_t)BB*AA*RR];
__device__ __nv_bfloat16 g_w0_hi[AA*RR];
__device__ __nv_bfloat16 g_w0_lo[AA*RR];
__device__ __nv_bfloat16 g_w1_hi[AA*RR];
__device__ __nv_bfloat16 g_w1_lo[AA*RR];
__device__ __nv_bfloat16 g_h2aw_hi[AA*RR];
__device__ __nv_bfloat16 g_h2aw_lo[AA*RR];
__device__ __nv_bfloat16 g_h2a1w_hi[AA*RR];
__device__ __nv_bfloat16 g_h2a1w_lo[AA*RR];
__device__ __nv_bfloat16 g_i2h_hi[2*LW];
__device__ __nv_bfloat16 g_i2h_lo[2*LW];
__device__ __nv_bfloat16 g_h2h_hi[2*LW];
__device__ __nv_bfloat16 g_h2h_lo[2*LW];
__device__ __nv_bfloat16 g_a2h_hi[2*LW];
__device__ __nv_bfloat16 g_a2h_lo[2*LW];
__device__ __nv_bfloat16 g_proj_hi[OUTN*RR];
__device__ __nv_bfloat16 g_proj_lo[OUTN*RR];
__device__ __nv_bfloat16 g_x_hi[BR];
__device__ __nv_bfloat16 g_x_lo[BR];
__device__ __nv_bfloat16 g_h01_hi[2*BR];
__device__ __nv_bfloat16 g_h01_lo[2*BR];
__device__ __nv_bfloat16 g_xt_hi[BR];
__device__ __nv_bfloat16 g_xt_lo[BR];
__device__ __nv_bfloat16 g_nh_hi[BR];
__device__ __nv_bfloat16 g_nh_lo[BR];
__device__ __nv_bfloat16 g_th_hi[BR];
__device__ __nv_bfloat16 g_th_lo[BR];
__device__ __nv_bfloat16 g_ar_hi[2*BR];
__device__ __nv_bfloat16 g_ar_lo[2*BR];

// ---------------- PTX helpers ----------------
__device__ __forceinline__ uint32_t smem_u32(const void* p){
    uint32_t a;
    asm("{ .reg .u64 t; cvta.to.shared.u64 t, %1; cvt.u32.u64 %0, t; }" : "=r"(a) : "l"(p));
    return a;
}
__device__ __forceinline__ void cp16(uint32_t dst, const void* src){
    asm volatile("cp.async.cg.shared.global [%0], [%1], 16;\n" :: "r"(dst), "l"(src));
}
__device__ __forceinline__ void cp16z(uint32_t dst, const void* src, bool ok){
    int sz = ok ? 16 : 0;
    asm volatile("cp.async.cg.shared.global [%0], [%1], 16, %2;\n" :: "r"(dst), "l"(src), "r"(sz));
}
#define CP_COMMIT()  asm volatile("cp.async.commit_group;\n" ::: "memory")
#define CP_WAIT0()   asm volatile("cp.async.wait_group 0;\n" ::: "memory")
#define CP_WAIT1()   asm volatile("cp.async.wait_group 1;\n" ::: "memory")

#define SWZ(off) ((off) ^ (((off) >> 3) & 0x70))

__device__ __forceinline__ uint32_t lds_u32(uint32_t addr){
    uint32_t v; asm volatile("ld.shared.b32 %0, [%1];" : "=r"(v) : "r"(addr)); return v;
}
__device__ __forceinline__ void mma16816(float* c, const uint32_t* a, const uint32_t* b){
    asm volatile(
        "mma.sync.aligned.m16n8k16.row.col.f32.bf16.bf16.f32 "
        "{%0,%1,%2,%3}, {%4,%5,%6,%7}, {%8,%9}, {%0,%1,%2,%3};"
        : "+f"(c[0]), "+f"(c[1]), "+f"(c[2]), "+f"(c[3])
        : "r"(a[0]), "r"(a[1]), "r"(a[2]), "r"(a[3]), "r"(b[0]), "r"(b[1]));
}
__device__ __forceinline__ void split1(float v, __nv_bfloat16* hi, __nv_bfloat16* lo){
    __nv_bfloat16 h = __float2bfloat16(v);
    *hi = h; *lo = __float2bfloat16(v - __bfloat162float(h));
}

// ---------------- split fp32 -> bf16 hi/lo ----------------
__global__ void split_bf16_kernel(const float* __restrict__ in,
                                  __nv_bfloat16* __restrict__ hi,
                                  __nv_bfloat16* __restrict__ lo, size_t n4)
{
    size_t i = (size_t)blockIdx.x*blockDim.x + threadIdx.x;
    if (i >= n4) return;
    float4 x = ((const float4*)in)[i];
    __nv_bfloat16 h[4], l[4];
    float xv[4] = {x.x, x.y, x.z, x.w};
    #pragma unroll
    for (int j=0;j<4;j++){
        h[j] = __float2bfloat16(xv[j]);
        l[j] = __float2bfloat16(xv[j] - __bfloat162float(h[j]));
    }
    ((uint2*)hi)[i] = *(uint2*)h;
    ((uint2*)lo)[i] = *(uint2*)l;
}

// =====================================================================
// big HMMA split-bf16 GEMM over att (unchanged from R3)
// =====================================================================
__global__ __launch_bounds__(256, 1)
void hmma_gemm_kernel(const __nv_bfloat16* __restrict__ Ahi, const __nv_bfloat16* __restrict__ Alo,
                      const __nv_bfloat16* __restrict__ W0hi, const __nv_bfloat16* __restrict__ W0lo,
                      const __nv_bfloat16* __restrict__ W1hi, const __nv_bfloat16* __restrict__ W1lo,
                      const float* __restrict__ ba0, const float* __restrict__ ba1,
                      const float* __restrict__ wd0,
                      const float* __restrict__ hh0, const float* __restrict__ hh1,
                      float* __restrict__ v1out,
                      float* __restrict__ sp0, float* __restrict__ sp1)
{
    extern __shared__ char dsm[];
    const int tid  = threadIdx.x;
    const int wid  = tid >> 5;
    const int lane = tid & 31;
    const int grp  = lane >> 2;
    const int tid4 = lane & 3;
    const int set  = blockIdx.x & 1;
    const int nt4  = blockIdx.x >> 1;
    const int mBase = blockIdx.y * MT;
    const int nBase4 = nt4 * NT;
    const int wm = wid >> 1;
    const int wn = wid & 1;

    const __nv_bfloat16* Whi = set ? W1hi : W0hi;
    const __nv_bfloat16* Wlo = set ? W1lo : W0lo;
    const float* bias = set ? ba1 : ba0;

    const uint32_t sbase = smem_u32(dsm);

    float acc[2][8][4];
    #pragma unroll
    for (int mt=0;mt<2;mt++)
        #pragma unroll
        for (int nt=0;nt<8;nt++)
            #pragma unroll
            for (int q=0;q<4;q++) acc[mt][nt][q]=0.f;

    auto load_stage = [&](int s){
        const uint32_t base = sbase + (s & 1) * STAGE_BYTES;
        const int kOff = s * KSTAGE;
        #pragma unroll
        for (int i = 0; i < 8; i++){
            int idx = tid + i * 256;
            int half = idx >> 10;
            int r = (idx >> 3) & 127;
            int ch = idx & 7;
            const __nv_bfloat16* src = (half ? Alo : Ahi) + (size_t)(mBase + r) * RR + kOff + ch * 8;
            cp16(base + half * 16384 + SWZ(r * 128 + ch * 16), src);
        }
        #pragma unroll
        for (int i = 0; i < 8; i++){
            int idx = tid + i * 256;
            int half = idx >> 10;
            int r = (idx >> 3) & 127;
            int ch = idx & 7;
            const __nv_bfloat16* src = (half ? Wlo : Whi) + (size_t)(nBase4 + r) * RR + kOff + ch * 8;
            cp16(base + 32768 + half * 16384 + SWZ(r * 128 + ch * 16), src);
        }
        CP_COMMIT();
    };

    load_stage(0);

    for (int s = 0; s < NSTAGES; s++){
        if (s + 1 < NSTAGES){ load_stage(s + 1); CP_WAIT1(); }
        else                 { CP_WAIT0(); }
        __syncthreads();

        const uint32_t sA = sbase + (s & 1) * STAGE_BYTES;
        const uint32_t sB = sA + 32768;
        #pragma unroll
        for (int k16 = 0; k16 < 4; k16++){
            const int kc = k16 * 32 + tid4 * 4;
            uint32_t aH[2][4], aL[2][4];
            #pragma unroll
            for (int mt = 0; mt < 2; mt++){
                int r0 = (wm*32 + mt*16 + grp) * 128 + kc;
                int r1 = r0 + 8*128;
                aH[mt][0] = lds_u32(sA + SWZ(r0));
                aH[mt][1] = lds_u32(sA + SWZ(r1));
                aH[mt][2] = lds_u32(sA + SWZ(r0 + 16));
                aH[mt][3] = lds_u32(sA + SWZ(r1 + 16));
                aL[mt][0] = lds_u32(sA + 16384 + SWZ(r0));
                aL[mt][1] = lds_u32(sA + 16384 + SWZ(r1));
                aL[mt][2] = lds_u32(sA + 16384 + SWZ(r0 + 16));
                aL[mt][3] = lds_u32(sA + 16384 + SWZ(r1 + 16));
            }
            #pragma unroll
            for (int nt = 0; nt < 8; nt++){
                int rb = (wn*64 + nt*8 + grp) * 128 + kc;
                uint32_t bH[2], bL[2];
                bH[0] = lds_u32(sB + SWZ(rb));
                bH[1] = lds_u32(sB + SWZ(rb + 16));
                bL[0] = lds_u32(sB + 16384 + SWZ(rb));
                bL[1] = lds_u32(sB + 16384 + SWZ(rb + 16));
                #pragma unroll
                for (int mt = 0; mt < 2; mt++){
                    mma16816(acc[mt][nt], aH[mt], bH);
                    mma16816(acc[mt][nt], aH[mt], bL);
                    mma16816(acc[mt][nt], aL[mt], bH);
                }
            }
        }
        __syncthreads();
    }

    if (set == 1){
        #pragma unroll
        for (int mt = 0; mt < 2; mt++){
            #pragma unroll
            for (int rh = 0; rh < 2; rh++){
                int m = mBase + wm*32 + mt*16 + rh*8 + grp;
                float* dst = v1out + (size_t)m * AA;
                #pragma unroll
                for (int nt = 0; nt < 8; nt++){
                    int n0 = nBase4 + wn*64 + nt*8 + tid4*2;
                    float2 v2;
                    v2.x = acc[mt][nt][rh*2+0] + bias[n0];
                    v2.y = acc[mt][nt][rh*2+1] + bias[n0+1];
                    *(float2*)(dst + n0) = v2;
                }
            }
        }
    } else {
        const int part = nt4*2 + wn;
        #pragma unroll
        for (int mt = 0; mt < 2; mt++){
            #pragma unroll
            for (int rh = 0; rh < 2; rh++){
                int m = mBase + wm*32 + mt*16 + rh*8 + grp;
                float h0 = hh0[m], h1 = hh1[m];
                float p0 = 0.f, p1 = 0.f;
                #pragma unroll
                for (int nt = 0; nt < 8; nt++){
                    int n0 = nBase4 + wn*64 + nt*8 + tid4*2;
                    float v0 = acc[mt][nt][rh*2+0] + bias[n0];
                    float v1v = acc[mt][nt][rh*2+1] + bias[n0+1];
                    float wv0 = wd0[n0], wv1 = wd0[n0+1];
                    p0 += tanhf(v0 + h0)*wv0 + tanhf(v1v + h0)*wv1;
                    p1 += tanhf(v0 + h1)*wv0 + tanhf(v1v + h1)*wv1;
                }
                p0 += __shfl_down_sync(0xffffffffu, p0, 2, 4);
                p0 += __shfl_down_sync(0xffffffffu, p0, 1, 4);
                p1 += __shfl_down_sync(0xffffffffu, p1, 2, 4);
                p1 += __shfl_down_sync(0xffffffffu, p1, 1, 4);
                if (tid4 == 0){
                    sp0[(size_t)part*BA + m] = p0;
                    sp1[(size_t)part*BA + m] = p1;
                }
            }
        }
    }
}

// =====================================================================
// Generic split-bf16 HMMA GEMM, 128x64 tile, multi-source K, K-split.
// grid: (nTiles, kSplit, mTiles). out partial kIdx at out + kIdx*kStride.
// =====================================================================
template<int NSRC>
__global__ __launch_bounds__(256, 1)
void hgemm_kernel(const __nv_bfloat16* __restrict__ Xhi0, const __nv_bfloat16* __restrict__ Xlo0,
                  const __nv_bfloat16* __restrict__ Whi0, const __nv_bfloat16* __restrict__ Wlo0,
                  const __nv_bfloat16* __restrict__ Xhi1, const __nv_bfloat16* __restrict__ Xlo1,
                  const __nv_bfloat16* __restrict__ Whi1, const __nv_bfloat16* __restrict__ Wlo1,
                  const __nv_bfloat16* __restrict__ Xhi2, const __nv_bfloat16* __restrict__ Xlo2,
                  const __nv_bfloat16* __restrict__ Whi2, const __nv_bfloat16* __restrict__ Wlo2,
                  float* __restrict__ out, int Nreal, int kStride)
{
    extern __shared__ char dsm[];
    const int tid  = threadIdx.x;
    const int wid  = tid >> 5;
    const int lane = tid & 31;
    const int grp  = lane >> 2;
    const int tid4 = lane & 3;
    const int nBase = blockIdx.x * 64;
    const int kIdx  = blockIdx.y;
    const int mBase = blockIdx.z * 128;
    const int wm = wid >> 1;     // 0..3
    const int wn = wid & 1;      // 0..1
    const uint32_t sbase = smem_u32(dsm);

    const int spc  = (NSRC * 8) / gridDim.y;
    const int sBeg = kIdx * spc;

    float acc[2][4][4];
    #pragma unroll
    for (int mt=0;mt<2;mt++)
        #pragma unroll
        for (int nt=0;nt<4;nt++)
            #pragma unroll
            for (int q=0;q<4;q++) acc[mt][nt][q]=0.f;

    auto load_stage = [&](int s, int buf){
        const uint32_t base = sbase + buf * HSTG;
        const int src = s >> 3;
        const int kOff = (s & 7) * 64;
        const __nv_bfloat16 *xh, *xl, *wh, *wl;
        if (NSRC == 1 || src == 0){ xh=Xhi0; xl=Xlo0; wh=Whi0; wl=Wlo0; }
        else if (src == 1){ xh=Xhi1; xl=Xlo1; wh=Whi1; wl=Wlo1; }
        else { xh=Xhi2; xl=Xlo2; wh=Whi2; wl=Wlo2; }
        #pragma unroll
        for (int i = 0; i < 8; i++){            // A: 2048 chunks
            int idx = tid + i * 256;
            int half = idx >> 10;
            int r = (idx >> 3) & 127;
            int ch = idx & 7;
            const __nv_bfloat16* src_p = (half ? xl : xh) + (size_t)(mBase + r) * 512 + kOff + ch * 8;
            cp16(base + half * 16384 + SWZ(r * 128 + ch * 16), src_p);
        }
        #pragma unroll
        for (int i = 0; i < 4; i++){            // B: 1024 chunks
            int idx = tid + i * 256;
            int half = idx >> 9;
            int r = (idx >> 3) & 63;
            int ch = idx & 7;
            bool ok = (nBase + r) < Nreal;
            const __nv_bfloat16* src_p = (half ? wl : wh) + (size_t)(nBase + r) * 512 + kOff + ch * 8;
            cp16z(base + 32768 + half * 8192 + SWZ(r * 128 + ch * 16), src_p, ok);
        }
        CP_COMMIT();
    };

    load_stage(sBeg, 0);

    for (int i = 0; i < spc; i++){
        if (i + 1 < spc){ load_stage(sBeg + i + 1, (i + 1) & 1); CP_WAIT1(); }
        else            { CP_WAIT0(); }
        __syncthreads();

        const uint32_t sA = sbase + (i & 1) * HSTG;
        const uint32_t sB = sA + 32768;
        #pragma unroll
        for (int k16 = 0; k16 < 4; k16++){
            const int kc = k16 * 32 + tid4 * 4;
            uint32_t aH[2][4], aL[2][4];
            #pragma unroll
            for (int mt = 0; mt < 2; mt++){
                int r0 = (wm*32 + mt*16 + grp) * 128 + kc;
                int r1 = r0 + 8*128;
                aH[mt][0] = lds_u32(sA + SWZ(r0));
                aH[mt][1] = lds_u32(sA + SWZ(r1));
                aH[mt][2] = lds_u32(sA + SWZ(r0 + 16));
                aH[mt][3] = lds_u32(sA + SWZ(r1 + 16));
                aL[mt][0] = lds_u32(sA + 16384 + SWZ(r0));
                aL[mt][1] = lds_u32(sA + 16384 + SWZ(r1));
                aL[mt][2] = lds_u32(sA + 16384 + SWZ(r0 + 16));
                aL[mt][3] = lds_u32(sA + 16384 + SWZ(r1 + 16));
            }
            #pragma unroll
            for (int nt = 0; nt < 4; nt++){
                int rb = (wn*32 + nt*8 + grp) * 128 + kc;
                uint32_t bH[2], bL[2];
                bH[0] = lds_u32(sB + SWZ(rb));
                bH[1] = lds_u32(sB + SWZ(rb + 16));
                bL[0] = lds_u32(sB + 8192 + SWZ(rb));
                bL[1] = lds_u32(sB + 8192 + SWZ(rb + 16));
                #pragma unroll
                for (int mt = 0; mt < 2; mt++){
                    mma16816(acc[mt][nt], aH[mt], bH);
                    mma16816(acc[mt][nt], aH[mt], bL);
                    mma16816(acc[mt][nt], aL[mt], bH);
                }
            }
        }
        __syncthreads();
    }

    float* obase = out + (size_t)kIdx * kStride;
    #pragma unroll
    for (int mt = 0; mt < 2; mt++){
        #pragma unroll
        for (int rh = 0; rh < 2; rh++){
            int m = mBase + wm*32 + mt*16 + rh*8 + grp;
            #pragma unroll
            for (int nt = 0; nt < 4; nt++){
                int n0 = nBase + wn*32 + nt*8 + tid4*2;
                if (n0 < Nreal){
                    float2 v2;
                    v2.x = acc[mt][nt][rh*2+0];
                    v2.y = acc[mt][nt][rh*2+1];
                    *(float2*)(obase + (size_t)m * Nreal + n0) = v2;
                }
            }
        }
    }
}

// ---------------- reduce partials + bias (biasN=512) ----------------
__global__ void reduce_bias_kernel(const float* __restrict__ in, const float* __restrict__ bias,
                                   float* __restrict__ out, int n, int parts, int pstride)
{
    int i = blockIdx.x*256 + threadIdx.x;
    if (i >= n) return;
    float s = bias[i & 511];
    for (int p = 0; p < parts; p++) s += in[(size_t)p*pstride + i];
    out[i] = s;
}

// ---------------- softmax over a (A=512), summing nparts partials (stride BA) ----------------
__global__ void softmax512_kernel(const float* __restrict__ in, float* __restrict__ out, int nparts)
{
    __shared__ float sm[8];
    int b = blockIdx.x, t = threadIdx.x;
    float v0=0.f, v1=0.f;
    for (int p=0;p<nparts;p++){
        const float* ip = in + (size_t)p*BA + (size_t)b*AA;
        v0 += ip[t]; v1 += ip[t+256];
    }
    float m = fmaxf(v0,v1);
    for (int o=16;o;o>>=1) m = fmaxf(m, __shfl_xor_sync(0xffffffffu,m,o));
    if ((t&31)==0) sm[t>>5]=m;
    __syncthreads();
    float M = sm[0];
    #pragma unroll
    for (int i=1;i<8;i++) M = fmaxf(M, sm[i]);
    __syncthreads();
    float e0=expf(v0-M), e1=expf(v1-M);
    float s = e0+e1;
    for (int o=16;o;o>>=1) s += __shfl_xor_sync(0xffffffffu,s,o);
    if ((t&31)==0) sm[t>>5]=s;
    __syncthreads();
    float S=0.f;
    #pragma unroll
    for (int i=0;i<8;i++) S += sm[i];
    float inv = 1.f/S;
    out[(size_t)b*AA + t]     = e0*inv;
    out[(size_t)b*AA + t+256] = e1*inv;
}

// ---------------- score scan over materialized v1 ----------------
__global__ void v1_scores_kernel(const float* __restrict__ v1, const float* __restrict__ hh,
                                 const float* __restrict__ wd, float* __restrict__ scores)
{
    __shared__ float sm[4];
    int a = blockIdx.x, b = blockIdx.y, t = threadIdx.x;
    float h = hh[(size_t)b*AA + a];
    float4 v = ((const float4*)(v1 + ((size_t)b*AA + a)*AA))[t];
    float4 w = ((const float4*)wd)[t];
    float s = tanhf(v.x+h)*w.x + tanhf(v.y+h)*w.y + tanhf(v.z+h)*w.z + tanhf(v.w+h)*w.w;
    for (int o=16;o;o>>=1) s += __shfl_xor_sync(0xffffffffu,s,o);
    if ((t&31)==0) sm[t>>5]=s;
    __syncthreads();
    if (t==0) scores[(size_t)b*AA + a] = sm[0]+sm[1]+sm[2]+sm[3];
}

// ---------------- att_res (+ fused bf16 splits) ----------------
template<bool DUAL, bool ADD>
__global__ void attres_kernel(const float* __restrict__ att,
                              const float* __restrict__ w0, const float* __restrict__ w1,
                              const float* __restrict__ addv, const float* __restrict__ xadd,
                              float* __restrict__ out0,
                              __nv_bfloat16* __restrict__ hi0, __nv_bfloat16* __restrict__ lo0,
                              __nv_bfloat16* __restrict__ hi1, __nv_bfloat16* __restrict__ lo1)
{
    __shared__ float sw0[AA];
    __shared__ float sw1[AA];
    int b = blockIdx.y;
    int r = blockIdx.x*256 + threadIdx.x;
    for (int a=threadIdx.x; a<AA; a+=256){
        sw0[a]=w0[(size_t)b*AA+a];
        if (DUAL) sw1[a]=w1[(size_t)b*AA+a];
    }
    __syncthreads();
    float acc0=0.f, acc1=0.f;
    const float* ap = att + (size_t)b*AA*RR + r;
    #pragma unroll 8
    for (int a=0;a<AA;a++){
        float av = ap[(size_t)a*RR];
        acc0 = fmaf(sw0[a], av, acc0);
        if (DUAL) acc1 = fmaf(sw1[a], av, acc1);
    }
    size_t idx = (size_t)b*RR + r;
    if (ADD) acc0 += addv[idx];
    if (out0) out0[idx] = acc0;
    float e0 = xadd ? acc0 + xadd[idx] : acc0;
    split1(e0, hi0 + idx, lo0 + idx);
    if (DUAL) split1(acc1, hi1 + idx, lo1 + idx);
}

// ---------------- LSTM pointwise: sums 4 K-split partials + biases ----------------
__global__ void lstm_pw_kernel(const float* __restrict__ sums4,
                               const float* __restrict__ bi, const float* __restrict__ bh,
                               const float* __restrict__ ba,
                               const float* __restrict__ prev_c,
                               float* __restrict__ next_c, float* __restrict__ next_h,
                               __nv_bfloat16* __restrict__ nh_hi, __nv_bfloat16* __restrict__ nh_lo)
{
    int idx = blockIdx.x*256 + threadIdx.x;
    int b = idx >> 9, r = idx & 511;
    float pc = prev_c[idx];
    float cs=0.f, hs=0.f;
    #pragma unroll
    for (int p=0;p<2;p++){
        float g[4];
        #pragma unroll
        for (int gi=0; gi<4; gi++){
            int off = p*2048 + gi*512 + r;
            float s = bi[off] + bh[off] + ba[off];
            #pragma unroll
            for (int q=0;q<4;q++) s += sums4[(size_t)q*(BB*4096) + (size_t)b*4096 + off];
            g[gi] = s;
        }
        float ig = 1.f/(1.f+expf(-g[0]));
        float fg = 1.f/(1.f+expf(-g[1]));
        float og = 1.f/(1.f+expf(-g[2]));
        float tt = tanhf(g[3]);
        float c  = fg*pc + ig*tt;
        cs += c; hs += og*tanhf(c);
    }
    float nc = cs*0.5f, nh = hs*0.5f;
    next_c[idx] = nc;
    next_h[idx] = nh;
    split1(nh, nh_hi + idx, nh_lo + idx);
}

// ---------------- log_softmax: sums 2 proj partials + bias, smem-cached ----------------
__global__ void logsoftmax_kernel(const float* __restrict__ parts, const float* __restrict__ bias,
                                  float* __restrict__ out)
{
    __shared__ float sx[OUTN];
    __shared__ float sm[8];
    int b = blockIdx.x, t = threadIdx.x;
    const float* a0 = parts + (size_t)b*OUTN;
    const float* a1 = parts + (size_t)(BB + b)*OUTN;
    for (int i=t;i<OUTN;i+=256) sx[i] = a0[i] + a1[i] + bias[i];
    __syncthreads();
    float m = -3.4e38f;
    for (int i=t;i<OUTN;i+=256) m = fmaxf(m, sx[i]);
    for (int o=16;o;o>>=1) m = fmaxf(m, __shfl_xor_sync(0xffffffffu,m,o));
    if ((t&31)==0) sm[t>>5]=m;
    __syncthreads();
    float M = sm[0];
    #pragma unroll
    for (int i=1;i<8;i++) M = fmaxf(M, sm[i]);
    __syncthreads();
    float s=0.f;
    for (int i=t;i<OUTN;i+=256) s += expf(sx[i]-M);
    for (int o=16;o;o>>=1) s += __shfl_xor_sync(0xffffffffu,s,o);
    if ((t&31)==0) sm[t>>5]=s;
    __syncthreads();
    float S=0.f;
    #pragma unroll
    for (int i=0;i<8;i++) S += sm[i];
    float L = M + logf(S);
    for (int i=t;i<OUTN;i+=256) out[(size_t)b*OUTN+i] = sx[i]-L;
}

// =====================================================================
extern "C" void kernel_launch(void* const* d_in, const int* in_sizes, int n_in,
                              void* d_out, int out_size)
{
    const float* x      = (const float*)d_in[0];
    const float* att    = (const float*)d_in[1];
    const float* inputs = (const float*)d_in[2];
    const float* a2a_w  = (const float*)d_in[3];
    const float* a2a_b  = (const float*)d_in[4];
    const float* h2a_w  = (const float*)d_in[5];
    const float* h2a_b  = (const float*)d_in[6];
    const float* d2d_w  = (const float*)d_in[7];
    const float* a2a1_w = (const float*)d_in[9];
    const float* a2a1_b = (const float*)d_in[10];
    const float* h2a1_w = (const float*)d_in[11];
    const float* h2a1_b = (const float*)d_in[12];
    const float* d2d1_w = (const float*)d_in[13];
    const float* i2h_w  = (const float*)d_in[15];
    const float* i2h_b  = (const float*)d_in[16];
    const float* h2h_w  = (const float*)d_in[17];
    const float* h2h_b  = (const float*)d_in[18];
    const float* a2h_w  = (const float*)d_in[19];
    const float* a2h_b  = (const float*)d_in[20];
    const float* proj_w = (const float*)d_in[21];
    const float* proj_b = (const float*)d_in[22];
    float* out = (float*)d_out;

    float *v1p, *spart, *w0p, *w1p, *hhp, *hhredp, *hhpartp, *h2a1partp, *sums4p, *nexthp, *scoresp, *logits2p;
    cudaGetSymbolAddress((void**)&v1p,      g_v1);
    cudaGetSymbolAddress((void**)&spart,    g_spart);
    cudaGetSymbolAddress((void**)&w0p,      g_w0);
    cudaGetSymbolAddress((void**)&w1p,      g_w1);
    cudaGetSymbolAddress((void**)&hhp,      g_hh);
    cudaGetSymbolAddress((void**)&hhredp,   g_hhred);
    cudaGetSymbolAddress((void**)&hhpartp,  g_hhpart);
    cudaGetSymbolAddress((void**)&h2a1partp,g_h2a1part);
    cudaGetSymbolAddress((void**)&sums4p,   g_sums4);
    cudaGetSymbolAddress((void**)&nexthp,   g_nexth);
    cudaGetSymbolAddress((void**)&scoresp,  g_scores);
    cudaGetSymbolAddress((void**)&logits2p, g_logits2);

    __nv_bfloat16 *ahi,*alo,*w0hi,*w0lo,*w1hi,*w1lo,*h2awhi,*h2awlo,*h2a1whi,*h2a1wlo;
    __nv_bfloat16 *i2hhi,*i2hlo,*h2hhi,*h2hlo,*a2hhi,*a2hlo,*projhi,*projlo;
    __nv_bfloat16 *xhi,*xlo,*h01hi,*h01lo,*xthi,*xtlo,*nhhi,*nhlo,*thhi,*thlo,*arhi,*arlo;
    cudaGetSymbolAddress((void**)&ahi, g_att_hi);      cudaGetSymbolAddress((void**)&alo, g_att_lo);
    cudaGetSymbolAddress((void**)&w0hi, g_w0_hi);      cudaGetSymbolAddress((void**)&w0lo, g_w0_lo);
    cudaGetSymbolAddress((void**)&w1hi, g_w1_hi);      cudaGetSymbolAddress((void**)&w1lo, g_w1_lo);
    cudaGetSymbolAddress((void**)&h2awhi, g_h2aw_hi);  cudaGetSymbolAddress((void**)&h2awlo, g_h2aw_lo);
    cudaGetSymbolAddress((void**)&h2a1whi, g_h2a1w_hi);cudaGetSymbolAddress((void**)&h2a1wlo, g_h2a1w_lo);
    cudaGetSymbolAddress((void**)&i2hhi, g_i2h_hi);    cudaGetSymbolAddress((void**)&i2hlo, g_i2h_lo);
    cudaGetSymbolAddress((void**)&h2hhi, g_h2h_hi);    cudaGetSymbolAddress((void**)&h2hlo, g_h2h_lo);
    cudaGetSymbolAddress((void**)&a2hhi, g_a2h_hi);    cudaGetSymbolAddress((void**)&a2hlo, g_a2h_lo);
    cudaGetSymbolAddress((void**)&projhi, g_proj_hi);  cudaGetSymbolAddress((void**)&projlo, g_proj_lo);
    cudaGetSymbolAddress((void**)&xhi, g_x_hi);        cudaGetSymbolAddress((void**)&xlo, g_x_lo);
    cudaGetSymbolAddress((void**)&h01hi, g_h01_hi);    cudaGetSymbolAddress((void**)&h01lo, g_h01_lo);
    cudaGetSymbolAddress((void**)&xthi, g_xt_hi);      cudaGetSymbolAddress((void**)&xtlo, g_xt_lo);
    cudaGetSymbolAddress((void**)&nhhi, g_nh_hi);      cudaGetSymbolAddress((void**)&nhlo, g_nh_lo);
    cudaGetSymbolAddress((void**)&thhi, g_th_hi);      cudaGetSymbolAddress((void**)&thlo, g_th_lo);
    cudaGetSymbolAddress((void**)&arhi, g_ar_hi);      cudaGetSymbolAddress((void**)&arlo, g_ar_lo);

    const float* prev_c0 = inputs;
    const float* prev_h0 = inputs + 1*BR;
    const float* prev_c1 = inputs + 2*BR;
    const float* prev_h1 = inputs + 3*BR;

    float* sp0 = spart;
    float* sp1 = spart + (size_t)8*BA;

    cudaFuncSetAttribute(hmma_gemm_kernel, cudaFuncAttributeMaxDynamicSharedMemorySize, 2*STAGE_BYTES);
    cudaFuncSetAttribute(hgemm_kernel<1>, cudaFuncAttributeMaxDynamicSharedMemorySize, 2*HSTG);
    cudaFuncSetAttribute(hgemm_kernel<3>, cudaFuncAttributeMaxDynamicSharedMemorySize, 2*HSTG);

    // ---- splits ----
    {
        size_t n4 = (size_t)BB*AA*RR/4;
        split_bf16_kernel<<<(unsigned)((n4+255)/256),256>>>(att, ahi, alo, n4);
        split_bf16_kernel<<<256,256>>>(a2a_w,  w0hi, w0lo, AA*RR/4);
        split_bf16_kernel<<<256,256>>>(a2a1_w, w1hi, w1lo, AA*RR/4);
        split_bf16_kernel<<<256,256>>>(h2a_w,  h2awhi, h2awlo, AA*RR/4);
        split_bf16_kernel<<<256,256>>>(h2a1_w, h2a1whi, h2a1wlo, AA*RR/4);
        split_bf16_kernel<<<4096,256>>>(i2h_w, i2hhi, i2hlo, 2*LW/4);
        split_bf16_kernel<<<4096,256>>>(h2h_w, h2hhi, h2hlo, 2*LW/4);
        split_bf16_kernel<<<4096,256>>>(a2h_w, a2hhi, a2hlo, 2*LW/4);
        split_bf16_kernel<<<5000,256>>>(proj_w, projhi, projlo, OUTN*RR/4);
        split_bf16_kernel<<<64,256>>>(x, xhi, xlo, BR/4);
        split_bf16_kernel<<<64,256>>>(prev_h0, h01hi, h01lo, BR/4);
        split_bf16_kernel<<<64,256>>>(prev_h1, h01hi+BR, h01lo+BR, BR/4);
    }

    // ---- hh for both prev-attends: M=256, N=512, K=512, ksplit=4 ----
    hgemm_kernel<1><<<dim3(8,4,2),256,2*HSTG>>>(
        h01hi, h01lo, h2awhi, h2awlo, 0,0,0,0, 0,0,0,0, hhpartp, AA, 2*BA);
    reduce_bias_kernel<<<(2*BA+255)/256,256>>>(hhpartp, h2a_b, hhredp, 2*BA, 4, 2*BA);

    // ---- big tensor GEMMs ----
    hmma_gemm_kernel<<<dim3(8,512),256,2*STAGE_BYTES>>>(
        ahi, alo, w0hi, w0lo, w1hi, w1lo,
        a2a_b, a2a1_b, d2d_w, hhredp, hhredp+BA, v1p, sp0, sp1);

    softmax512_kernel<<<BB,256>>>(sp0, w0p, 8);
    softmax512_kernel<<<BB,256>>>(sp1, w1p, 8);

    // both prev att_res (bf16 hi/lo only)
    attres_kernel<true,false><<<dim3(2,BB),256>>>(att, w0p, w1p, nullptr, nullptr,
        nullptr, arhi, arlo, arhi+BR, arlo+BR);

    // ---- layer 0 ----
    hgemm_kernel<3><<<dim3(64,4,1),256,2*HSTG>>>(
        xhi, xlo, i2hhi, i2hlo,
        h01hi, h01lo, h2hhi, h2hlo,
        arhi, arlo, a2hhi, a2hlo,
        sums4p, 4096, BB*4096);
    lstm_pw_kernel<<<BR/256,256>>>(sums4p, i2h_b, h2h_b, a2h_b, prev_c0,
                                   out + 0, nexthp, nhhi, nhlo);

    hgemm_kernel<1><<<dim3(8,4,1),256,2*HSTG>>>(
        nhhi, nhlo, h2a1whi, h2a1wlo, 0,0,0,0, 0,0,0,0, h2a1partp, AA, BA);
    reduce_bias_kernel<<<(BA+255)/256,256>>>(h2a1partp, h2a1_b, hhp, BA, 4, BA);
    v1_scores_kernel<<<dim3(AA,BB),128>>>(v1p, hhp, d2d1_w, scoresp);
    softmax512_kernel<<<BB,256>>>(scoresp, w0p, 1);
    // top_h0 -> out+BR; xt = x + top_h0 -> hi/lo
    attres_kernel<false,true><<<dim3(2,BB),256>>>(att, w0p, nullptr, nexthp, x,
        out + BR, xthi, xtlo, nullptr, nullptr);

    // ---- layer 1 ----
    hgemm_kernel<3><<<dim3(64,4,1),256,2*HSTG>>>(
        xthi, xtlo, i2hhi + LW, i2hlo + LW,
        h01hi + BR, h01lo + BR, h2hhi + LW, h2hlo + LW,
        arhi + BR, arlo + BR, a2hhi + LW, a2hlo + LW,
        sums4p, 4096, BB*4096);
    lstm_pw_kernel<<<BR/256,256>>>(sums4p, i2h_b + LB, h2h_b + LB, a2h_b + LB, prev_c1,
                                   out + 2*BR, nexthp, nhhi, nhlo);

    hgemm_kernel<1><<<dim3(8,4,1),256,2*HSTG>>>(
        nhhi, nhlo, h2a1whi, h2a1wlo, 0,0,0,0, 0,0,0,0, h2a1partp, AA, BA);
    reduce_bias_kernel<<<(BA+255)/256,256>>>(h2a1partp, h2a1_b, hhp, BA, 4, BA);
    v1_scores_kernel<<<dim3(AA,BB),128>>>(v1p, hhp, d2d1_w, scoresp);
    softmax512_kernel<<<BB,256>>>(scoresp, w0p, 1);
    // top_h1 -> out+3BR and hi/lo for proj
    attres_kernel<false,true><<<dim3(2,BB),256>>>(att, w0p, nullptr, nexthp, nullptr,
        out + 3*BR, thhi, thlo, nullptr, nullptr);

    // ---- projection + log_softmax ----
    hgemm_kernel<1><<<dim3(157,2,1),256,2*HSTG>>>(
        thhi, thlo, projhi, projlo, 0,0,0,0, 0,0,0,0, logits2p, OUTN, BB*OUTN);
    logsoftmax_kernel<<<BB,256>>>(logits2p, proj_b, out + 4*BR);
}

// round 5
// speedup vs baseline: 3.0010x; 1.1952x over previous
#include <cuda_runtime.h>
#include <cuda_bf16.h>
#include <cuda_fp16.h>
#include <math.h>
#include <cstdint>

#define BB 128
#define AA 512
#define RR 512
#define OUTN 10000
#define BR (BB*RR)
#define BA (BB*AA)
#define LW 2097152
#define LB 4096

// big HMMA GEMM tiling: 128x128, stage = A 16K + Whi 16K + Wlo 16K
#define MT 128
#define NT 128
#define NSTAGES 8
#define STAGE_BYTES 49152

// generic hgemm tiling: 128x64, stage = A 16K + Bhi 8K + Blo 8K
#define HSTG 32768

// ---------------- scratch (device globals; no allocations) ----------------
__device__ __half g_v1h[(size_t)BB*AA*AA];   // 67 MB, fp16 v1 (+bias)
__device__ float g_spart[2*8*BA];
__device__ float g_w0[BA];
__device__ float g_w1[BA];
__device__ float g_hhred[2*BA];
__device__ float g_hhpart[4*2*BA];
__device__ float g_h2a1part[4*BA];
__device__ float g_sums4[4*BB*4096];
__device__ float g_nexth[BR];
__device__ float g_scores[BA];
__device__ float g_logits2[(size_t)2*BB*OUTN];
// fp16 operands: activations single, weights hi/lo
__device__ __half g_att_h[(size_t)BB*AA*RR];
__device__ __half g_w0_hi[AA*RR];
__device__ __half g_w0_lo[AA*RR];
__device__ __half g_w1_hi[AA*RR];
__device__ __half g_w1_lo[AA*RR];
__device__ __half g_h2aw_hi[AA*RR];
__device__ __half g_h2aw_lo[AA*RR];
__device__ __half g_h2a1w_hi[AA*RR];
__device__ __half g_h2a1w_lo[AA*RR];
__device__ __half g_i2h_hi[2*LW];
__device__ __half g_i2h_lo[2*LW];
__device__ __half g_h2h_hi[2*LW];
__device__ __half g_h2h_lo[2*LW];
__device__ __half g_a2h_hi[2*LW];
__device__ __half g_a2h_lo[2*LW];
__device__ __half g_proj_hi[OUTN*RR];
__device__ __half g_proj_lo[OUTN*RR];
__device__ __half g_x_h[BR];
__device__ __half g_h01_h[2*BR];
__device__ __half g_xt_h[BR];
__device__ __half g_nh_h[BR];
__device__ __half g_th_h[BR];
__device__ __half g_ar_h[2*BR];

// ---------------- PTX helpers ----------------
__device__ __forceinline__ uint32_t smem_u32(const void* p){
    uint32_t a;
    asm("{ .reg .u64 t; cvta.to.shared.u64 t, %1; cvt.u32.u64 %0, t; }" : "=r"(a) : "l"(p));
    return a;
}
__device__ __forceinline__ void cp16(uint32_t dst, const void* src){
    asm volatile("cp.async.cg.shared.global [%0], [%1], 16;\n" :: "r"(dst), "l"(src));
}
__device__ __forceinline__ void cp16z(uint32_t dst, const void* src, bool ok){
    int sz = ok ? 16 : 0;
    asm volatile("cp.async.cg.shared.global [%0], [%1], 16, %2;\n" :: "r"(dst), "l"(src), "r"(sz));
}
#define CP_COMMIT()  asm volatile("cp.async.commit_group;\n" ::: "memory")
#define CP_WAIT0()   asm volatile("cp.async.wait_group 0;\n" ::: "memory")
#define CP_WAIT1()   asm volatile("cp.async.wait_group 1;\n" ::: "memory")

#define SWZ(off) ((off) ^ (((off) >> 3) & 0x70))

__device__ __forceinline__ uint32_t lds_u32(uint32_t addr){
    uint32_t v; asm volatile("ld.shared.b32 %0, [%1];" : "=r"(v) : "r"(addr)); return v;
}
// mma.sync m16n8k16 fp16 row.col, fp32 accumulate (in place)
__device__ __forceinline__ void mma16816(float* c, const uint32_t* a, const uint32_t* b){
    asm volatile(
        "mma.sync.aligned.m16n8k16.row.col.f32.f16.f16.f32 "
        "{%0,%1,%2,%3}, {%4,%5,%6,%7}, {%8,%9}, {%0,%1,%2,%3};"
        : "+f"(c[0]), "+f"(c[1]), "+f"(c[2]), "+f"(c[3])
        : "r"(a[0]), "r"(a[1]), "r"(a[2]), "r"(a[3]), "r"(b[0]), "r"(b[1]));
}

// ---------------- fp32 -> fp16 single ----------------
__global__ void tohalf_kernel(const float* __restrict__ in, __half* __restrict__ out, size_t n4)
{
    size_t i = (size_t)blockIdx.x*blockDim.x + threadIdx.x;
    if (i >= n4) return;
    float4 x = ((const float4*)in)[i];
    __half h[4] = { __float2half_rn(x.x), __float2half_rn(x.y),
                    __float2half_rn(x.z), __float2half_rn(x.w) };
    ((uint2*)out)[i] = *(uint2*)h;
}
// ---------------- fp32 -> fp16 hi/lo split ----------------
__global__ void splith_kernel(const float* __restrict__ in,
                              __half* __restrict__ hi, __half* __restrict__ lo, size_t n4)
{
    size_t i = (size_t)blockIdx.x*blockDim.x + threadIdx.x;
    if (i >= n4) return;
    float4 x = ((const float4*)in)[i];
    float xv[4] = {x.x, x.y, x.z, x.w};
    __half h[4], l[4];
    #pragma unroll
    for (int j=0;j<4;j++){
        h[j] = __float2half_rn(xv[j]);
        l[j] = __float2half_rn(xv[j] - __half2float(h[j]));
    }
    ((uint2*)hi)[i] = *(uint2*)h;
    ((uint2*)lo)[i] = *(uint2*)l;
}

// =====================================================================
// big HMMA fp16 2-term GEMM over att: C = att @ (Whi+Wlo)^T
// grid.x = (nt4<<1)|set (8), grid.y = mtile (512)
// =====================================================================
__global__ __launch_bounds__(256, 1)
void hmma_gemm_kernel(const __half* __restrict__ Ah,
                      const __half* __restrict__ W0hi, const __half* __restrict__ W0lo,
                      const __half* __restrict__ W1hi, const __half* __restrict__ W1lo,
                      const float* __restrict__ ba0, const float* __restrict__ ba1,
                      const float* __restrict__ wd0,
                      const float* __restrict__ hh0, const float* __restrict__ hh1,
                      __half* __restrict__ v1out,
                      float* __restrict__ sp0, float* __restrict__ sp1)
{
    extern __shared__ char dsm[];
    const int tid  = threadIdx.x;
    const int wid  = tid >> 5;
    const int lane = tid & 31;
    const int grp  = lane >> 2;
    const int tid4 = lane & 3;
    const int set  = blockIdx.x & 1;
    const int nt4  = blockIdx.x >> 1;
    const int mBase = blockIdx.y * MT;
    const int nBase4 = nt4 * NT;
    const int wm = wid >> 1;
    const int wn = wid & 1;

    const __half* Whi = set ? W1hi : W0hi;
    const __half* Wlo = set ? W1lo : W0lo;
    const float* bias = set ? ba1 : ba0;

    const uint32_t sbase = smem_u32(dsm);

    float acc[2][8][4];
    #pragma unroll
    for (int mt=0;mt<2;mt++)
        #pragma unroll
        for (int nt=0;nt<8;nt++)
            #pragma unroll
            for (int q=0;q<4;q++) acc[mt][nt][q]=0.f;

    auto load_stage = [&](int s){
        const uint32_t base = sbase + (s & 1) * STAGE_BYTES;
        const int kOff = s * 64;
        #pragma unroll
        for (int i = 0; i < 4; i++){              // A: 1024 chunks
            int idx = tid + i * 256;
            int r = idx >> 3;
            int ch = idx & 7;
            const __half* src = Ah + (size_t)(mBase + r) * RR + kOff + ch * 8;
            cp16(base + SWZ(r * 128 + ch * 16), src);
        }
        #pragma unroll
        for (int i = 0; i < 8; i++){              // B: 2048 chunks (hi, lo)
            int idx = tid + i * 256;
            int half = idx >> 10;
            int r = (idx >> 3) & 127;
            int ch = idx & 7;
            const __half* src = (half ? Wlo : Whi) + (size_t)(nBase4 + r) * RR + kOff + ch * 8;
            cp16(base + 16384 + half * 16384 + SWZ(r * 128 + ch * 16), src);
        }
        CP_COMMIT();
    };

    load_stage(0);

    for (int s = 0; s < NSTAGES; s++){
        if (s + 1 < NSTAGES){ load_stage(s + 1); CP_WAIT1(); }
        else                 { CP_WAIT0(); }
        __syncthreads();

        const uint32_t sA  = sbase + (s & 1) * STAGE_BYTES;
        const uint32_t sBh = sA + 16384;
        const uint32_t sBl = sA + 32768;
        #pragma unroll
        for (int k16 = 0; k16 < 4; k16++){
            const int kc = k16 * 32 + tid4 * 4;
            uint32_t aH[2][4];
            #pragma unroll
            for (int mt = 0; mt < 2; mt++){
                int r0 = (wm*32 + mt*16 + grp) * 128 + kc;
                int r1 = r0 + 8*128;
                aH[mt][0] = lds_u32(sA + SWZ(r0));
                aH[mt][1] = lds_u32(sA + SWZ(r1));
                aH[mt][2] = lds_u32(sA + SWZ(r0 + 16));
                aH[mt][3] = lds_u32(sA + SWZ(r1 + 16));
            }
            #pragma unroll
            for (int nt = 0; nt < 8; nt++){
                int rb = (wn*64 + nt*8 + grp) * 128 + kc;
                uint32_t bH[2], bL[2];
                bH[0] = lds_u32(sBh + SWZ(rb));
                bH[1] = lds_u32(sBh + SWZ(rb + 16));
                bL[0] = lds_u32(sBl + SWZ(rb));
                bL[1] = lds_u32(sBl + SWZ(rb + 16));
                #pragma unroll
                for (int mt = 0; mt < 2; mt++){
                    mma16816(acc[mt][nt], aH[mt], bH);
                    mma16816(acc[mt][nt], aH[mt], bL);
                }
            }
        }
        __syncthreads();
    }

    if (set == 1){
        #pragma unroll
        for (int mt = 0; mt < 2; mt++){
            #pragma unroll
            for (int rh = 0; rh < 2; rh++){
                int m = mBase + wm*32 + mt*16 + rh*8 + grp;
                __half* dst = v1out + (size_t)m * AA;
                #pragma unroll
                for (int nt = 0; nt < 8; nt++){
                    int n0 = nBase4 + wn*64 + nt*8 + tid4*2;
                    __half2 h2 = __floats2half2_rn(acc[mt][nt][rh*2+0] + bias[n0],
                                                   acc[mt][nt][rh*2+1] + bias[n0+1]);
                    *(__half2*)(dst + n0) = h2;
                }
            }
        }
    } else {
        const int part = nt4*2 + wn;
        #pragma unroll
        for (int mt = 0; mt < 2; mt++){
            #pragma unroll
            for (int rh = 0; rh < 2; rh++){
                int m = mBase + wm*32 + mt*16 + rh*8 + grp;
                float h0 = hh0[m], h1 = hh1[m];
                float p0 = 0.f, p1 = 0.f;
                #pragma unroll
                for (int nt = 0; nt < 8; nt++){
                    int n0 = nBase4 + wn*64 + nt*8 + tid4*2;
                    float v0 = acc[mt][nt][rh*2+0] + bias[n0];
                    float v1v = acc[mt][nt][rh*2+1] + bias[n0+1];
                    float wv0 = wd0[n0], wv1 = wd0[n0+1];
                    p0 += tanhf(v0 + h0)*wv0 + tanhf(v1v + h0)*wv1;
                    p1 += tanhf(v0 + h1)*wv0 + tanhf(v1v + h1)*wv1;
                }
                p0 += __shfl_down_sync(0xffffffffu, p0, 2, 4);
                p0 += __shfl_down_sync(0xffffffffu, p0, 1, 4);
                p1 += __shfl_down_sync(0xffffffffu, p1, 2, 4);
                p1 += __shfl_down_sync(0xffffffffu, p1, 1, 4);
                if (tid4 == 0){
                    sp0[(size_t)part*BA + m] = p0;
                    sp1[(size_t)part*BA + m] = p1;
                }
            }
        }
    }
}

// =====================================================================
// Generic fp16 2-term GEMM, 128x64 tile, multi-source K, K-split.
// =====================================================================
template<int NSRC>
__global__ __launch_bounds__(256, 1)
void hgemm_kernel(const __half* __restrict__ Xh0,
                  const __half* __restrict__ Whi0, const __half* __restrict__ Wlo0,
                  const __half* __restrict__ Xh1,
                  const __half* __restrict__ Whi1, const __half* __restrict__ Wlo1,
                  const __half* __restrict__ Xh2,
                  const __half* __restrict__ Whi2, const __half* __restrict__ Wlo2,
                  float* __restrict__ out, int Nreal, int kStride)
{
    extern __shared__ char dsm[];
    const int tid  = threadIdx.x;
    const int wid  = tid >> 5;
    const int lane = tid & 31;
    const int grp  = lane >> 2;
    const int tid4 = lane & 3;
    const int nBase = blockIdx.x * 64;
    const int kIdx  = blockIdx.y;
    const int mBase = blockIdx.z * 128;
    const int wm = wid >> 1;
    const int wn = wid & 1;
    const uint32_t sbase = smem_u32(dsm);

    const int spc  = (NSRC * 8) / gridDim.y;
    const int sBeg = kIdx * spc;

    float acc[2][4][4];
    #pragma unroll
    for (int mt=0;mt<2;mt++)
        #pragma unroll
        for (int nt=0;nt<4;nt++)
            #pragma unroll
            for (int q=0;q<4;q++) acc[mt][nt][q]=0.f;

    auto load_stage = [&](int s, int buf){
        const uint32_t base = sbase + buf * HSTG;
        const int src = s >> 3;
        const int kOff = (s & 7) * 64;
        const __half *xh, *wh, *wl;
        if (NSRC == 1 || src == 0){ xh=Xh0; wh=Whi0; wl=Wlo0; }
        else if (src == 1){ xh=Xh1; wh=Whi1; wl=Wlo1; }
        else { xh=Xh2; wh=Whi2; wl=Wlo2; }
        #pragma unroll
        for (int i = 0; i < 4; i++){              // A: 1024 chunks
            int idx = tid + i * 256;
            int r = idx >> 3;
            int ch = idx & 7;
            const __half* src_p = xh + (size_t)(mBase + r) * 512 + kOff + ch * 8;
            cp16(base + SWZ(r * 128 + ch * 16), src_p);
        }
        #pragma unroll
        for (int i = 0; i < 4; i++){              // B: 1024 chunks (hi 512, lo 512)
            int idx = tid + i * 256;
            int half = idx >> 9;
            int r = (idx >> 3) & 63;
            int ch = idx & 7;
            bool ok = (nBase + r) < Nreal;
            const __half* src_p = (half ? wl : wh) + (size_t)(nBase + r) * 512 + kOff + ch * 8;
            cp16z(base + 16384 + half * 8192 + SWZ(r * 128 + ch * 16), src_p, ok);
        }
        CP_COMMIT();
    };

    load_stage(sBeg, 0);

    for (int i = 0; i < spc; i++){
        if (i + 1 < spc){ load_stage(sBeg + i + 1, (i + 1) & 1); CP_WAIT1(); }
        else            { CP_WAIT0(); }
        __syncthreads();

        const uint32_t sA  = sbase + (i & 1) * HSTG;
        const uint32_t sBh = sA + 16384;
        const uint32_t sBl = sA + 24576;
        #pragma unroll
        for (int k16 = 0; k16 < 4; k16++){
            const int kc = k16 * 32 + tid4 * 4;
            uint32_t aH[2][4];
            #pragma unroll
            for (int mt = 0; mt < 2; mt++){
                int r0 = (wm*32 + mt*16 + grp) * 128 + kc;
                int r1 = r0 + 8*128;
                aH[mt][0] = lds_u32(sA + SWZ(r0));
                aH[mt][1] = lds_u32(sA + SWZ(r1));
                aH[mt][2] = lds_u32(sA + SWZ(r0 + 16));
                aH[mt][3] = lds_u32(sA + SWZ(r1 + 16));
            }
            #pragma unroll
            for (int nt = 0; nt < 4; nt++){
                int rb = (wn*32 + nt*8 + grp) * 128 + kc;
                uint32_t bH[2], bL[2];
                bH[0] = lds_u32(sBh + SWZ(rb));
                bH[1] = lds_u32(sBh + SWZ(rb + 16));
                bL[0] = lds_u32(sBl + SWZ(rb));
                bL[1] = lds_u32(sBl + SWZ(rb + 16));
                #pragma unroll
                for (int mt = 0; mt < 2; mt++){
                    mma16816(acc[mt][nt], aH[mt], bH);
                    mma16816(acc[mt][nt], aH[mt], bL);
                }
            }
        }
        __syncthreads();
    }

    float* obase = out + (size_t)kIdx * kStride;
    #pragma unroll
    for (int mt = 0; mt < 2; mt++){
        #pragma unroll
        for (int rh = 0; rh < 2; rh++){
            int m = mBase + wm*32 + mt*16 + rh*8 + grp;
            #pragma unroll
            for (int nt = 0; nt < 4; nt++){
                int n0 = nBase + wn*32 + nt*8 + tid4*2;
                if (n0 < Nreal){
                    float2 v2;
                    v2.x = acc[mt][nt][rh*2+0];
                    v2.y = acc[mt][nt][rh*2+1];
                    *(float2*)(obase + (size_t)m * Nreal + n0) = v2;
                }
            }
        }
    }
}

// ---------------- reduce partials + bias (biasN=512) ----------------
__global__ void reduce_bias_kernel(const float* __restrict__ in, const float* __restrict__ bias,
                                   float* __restrict__ out, int n, int parts, int pstride)
{
    int i = blockIdx.x*256 + threadIdx.x;
    if (i >= n) return;
    float s = bias[i & 511];
    for (int p = 0; p < parts; p++) s += in[(size_t)p*pstride + i];
    out[i] = s;
}

// ---------------- softmax over a (A=512), summing nparts partials (stride BA) ----------------
__global__ void softmax512_kernel(const float* __restrict__ in, float* __restrict__ out, int nparts)
{
    __shared__ float sm[8];
    int b = blockIdx.x, t = threadIdx.x;
    float v0=0.f, v1=0.f;
    for (int p=0;p<nparts;p++){
        const float* ip = in + (size_t)p*BA + (size_t)b*AA;
        v0 += ip[t]; v1 += ip[t+256];
    }
    float m = fmaxf(v0,v1);
    for (int o=16;o;o>>=1) m = fmaxf(m, __shfl_xor_sync(0xffffffffu,m,o));
    if ((t&31)==0) sm[t>>5]=m;
    __syncthreads();
    float M = sm[0];
    #pragma unroll
    for (int i=1;i<8;i++) M = fmaxf(M, sm[i]);
    __syncthreads();
    float e0=expf(v0-M), e1=expf(v1-M);
    float s = e0+e1;
    for (int o=16;o;o>>=1) s += __shfl_xor_sync(0xffffffffu,s,o);
    if ((t&31)==0) sm[t>>5]=s;
    __syncthreads();
    float S=0.f;
    #pragma unroll
    for (int i=0;i<8;i++) S += sm[i];
    float inv = 1.f/S;
    out[(size_t)b*AA + t]     = e0*inv;
    out[(size_t)b*AA + t+256] = e1*inv;
}

// ---------------- score scan over fp16 v1, fusing h2a1 partial-reduce ----------------
__global__ void v1_scores_kernel(const __half* __restrict__ v1, const float* __restrict__ parts,
                                 const float* __restrict__ hbias,
                                 const float* __restrict__ wd, float* __restrict__ scores)
{
    __shared__ float sm[4];
    int a = blockIdx.x, b = blockIdx.y, t = threadIdx.x;   // 128 threads
    size_t hidx = (size_t)b*AA + a;
    float h = hbias[a];
    #pragma unroll
    for (int p=0;p<4;p++) h += parts[(size_t)p*BA + hidx];
    uint2 u = ((const uint2*)(v1 + hidx*AA))[t];
    float2 f01 = __half22float2(*reinterpret_cast<__half2*>(&u.x));
    float2 f23 = __half22float2(*reinterpret_cast<__half2*>(&u.y));
    float4 w = ((const float4*)wd)[t];
    float s = tanhf(f01.x+h)*w.x + tanhf(f01.y+h)*w.y + tanhf(f23.x+h)*w.z + tanhf(f23.y+h)*w.w;
    for (int o=16;o;o>>=1) s += __shfl_xor_sync(0xffffffffu,s,o);
    if ((t&31)==0) sm[t>>5]=s;
    __syncthreads();
    if (t==0) scores[hidx] = sm[0]+sm[1]+sm[2]+sm[3];
}

// ---------------- att_res (+ fused fp16 converts) ----------------
template<bool DUAL, bool ADD>
__global__ void attres_kernel(const float* __restrict__ att,
                              const float* __restrict__ w0, const float* __restrict__ w1,
                              const float* __restrict__ addv, const float* __restrict__ xadd,
                              float* __restrict__ out0,
                              __half* __restrict__ h0out, __half* __restrict__ h1out)
{
    __shared__ float sw0[AA];
    __shared__ float sw1[AA];
    int b = blockIdx.y;
    int r = blockIdx.x*256 + threadIdx.x;
    for (int a=threadIdx.x; a<AA; a+=256){
        sw0[a]=w0[(size_t)b*AA+a];
        if (DUAL) sw1[a]=w1[(size_t)b*AA+a];
    }
    __syncthreads();
    float acc0=0.f, acc1=0.f;
    const float* ap = att + (size_t)b*AA*RR + r;
    #pragma unroll 8
    for (int a=0;a<AA;a++){
        float av = ap[(size_t)a*RR];
        acc0 = fmaf(sw0[a], av, acc0);
        if (DUAL) acc1 = fmaf(sw1[a], av, acc1);
    }
    size_t idx = (size_t)b*RR + r;
    if (ADD) acc0 += addv[idx];
    if (out0) out0[idx] = acc0;
    float e0 = xadd ? acc0 + xadd[idx] : acc0;
    h0out[idx] = __float2half_rn(e0);
    if (DUAL) h1out[idx] = __float2half_rn(acc1);
}

// ---------------- LSTM pointwise: sums 4 K-split partials + biases ----------------
__global__ void lstm_pw_kernel(const float* __restrict__ sums4,
                               const float* __restrict__ bi, const float* __restrict__ bh,
                               const float* __restrict__ ba,
                               const float* __restrict__ prev_c,
                               float* __restrict__ next_c, float* __restrict__ next_h,
                               __half* __restrict__ nh_h)
{
    int idx = blockIdx.x*256 + threadIdx.x;
    int b = idx >> 9, r = idx & 511;
    float pc = prev_c[idx];
    float cs=0.f, hs=0.f;
    #pragma unroll
    for (int p=0;p<2;p++){
        float g[4];
        #pragma unroll
        for (int gi=0; gi<4; gi++){
            int off = p*2048 + gi*512 + r;
            float s = bi[off] + bh[off] + ba[off];
            #pragma unroll
            for (int q=0;q<4;q++) s += sums4[(size_t)q*(BB*4096) + (size_t)b*4096 + off];
            g[gi] = s;
        }
        float ig = 1.f/(1.f+expf(-g[0]));
        float fg = 1.f/(1.f+expf(-g[1]));
        float og = 1.f/(1.f+expf(-g[2]));
        float tt = tanhf(g[3]);
        float c  = fg*pc + ig*tt;
        cs += c; hs += og*tanhf(c);
    }
    float nc = cs*0.5f, nh = hs*0.5f;
    next_c[idx] = nc;
    next_h[idx] = nh;
    nh_h[idx] = __float2half_rn(nh);
}

// ---------------- log_softmax: sums 2 proj partials + bias, smem-cached ----------------
__global__ void logsoftmax_kernel(const float* __restrict__ parts, const float* __restrict__ bias,
                                  float* __restrict__ out)
{
    __shared__ float sx[OUTN];
    __shared__ float sm[8];
    int b = blockIdx.x, t = threadIdx.x;
    const float* a0 = parts + (size_t)b*OUTN;
    const float* a1 = parts + (size_t)(BB + b)*OUTN;
    for (int i=t;i<OUTN;i+=256) sx[i] = a0[i] + a1[i] + bias[i];
    __syncthreads();
    float m = -3.4e38f;
    for (int i=t;i<OUTN;i+=256) m = fmaxf(m, sx[i]);
    for (int o=16;o;o>>=1) m = fmaxf(m, __shfl_xor_sync(0xffffffffu,m,o));
    if ((t&31)==0) sm[t>>5]=m;
    __syncthreads();
    float M = sm[0];
    #pragma unroll
    for (int i=1;i<8;i++) M = fmaxf(M, sm[i]);
    __syncthreads();
    float s=0.f;
    for (int i=t;i<OUTN;i+=256) s += expf(sx[i]-M);
    for (int o=16;o;o>>=1) s += __shfl_xor_sync(0xffffffffu,s,o);
    if ((t&31)==0) sm[t>>5]=s;
    __syncthreads();
    float S=0.f;
    #pragma unroll
    for (int i=0;i<8;i++) S += sm[i];
    float L = M + logf(S);
    for (int i=t;i<OUTN;i+=256) out[(size_t)b*OUTN+i] = sx[i]-L;
}

// =====================================================================
extern "C" void kernel_launch(void* const* d_in, const int* in_sizes, int n_in,
                              void* d_out, int out_size)
{
    const float* x      = (const float*)d_in[0];
    const float* att    = (const float*)d_in[1];
    const float* inputs = (const float*)d_in[2];
    const float* a2a_w  = (const float*)d_in[3];
    const float* a2a_b  = (const float*)d_in[4];
    const float* h2a_w  = (const float*)d_in[5];
    const float* h2a_b  = (const float*)d_in[6];
    const float* d2d_w  = (const float*)d_in[7];
    const float* a2a1_w = (const float*)d_in[9];
    const float* a2a1_b = (const float*)d_in[10];
    const float* h2a1_w = (const float*)d_in[11];
    const float* h2a1_b = (const float*)d_in[12];
    const float* d2d1_w = (const float*)d_in[13];
    const float* i2h_w  = (const float*)d_in[15];
    const float* i2h_b  = (const float*)d_in[16];
    const float* h2h_w  = (const float*)d_in[17];
    const float* h2h_b  = (const float*)d_in[18];
    const float* a2h_w  = (const float*)d_in[19];
    const float* a2h_b  = (const float*)d_in[20];
    const float* proj_w = (const float*)d_in[21];
    const float* proj_b = (const float*)d_in[22];
    float* out = (float*)d_out;

    float *spart, *w0p, *w1p, *hhredp, *hhpartp, *h2a1partp, *sums4p, *nexthp, *scoresp, *logits2p;
    __half* v1hp;
    cudaGetSymbolAddress((void**)&v1hp,     g_v1h);
    cudaGetSymbolAddress((void**)&spart,    g_spart);
    cudaGetSymbolAddress((void**)&w0p,      g_w0);
    cudaGetSymbolAddress((void**)&w1p,      g_w1);
    cudaGetSymbolAddress((void**)&hhredp,   g_hhred);
    cudaGetSymbolAddress((void**)&hhpartp,  g_hhpart);
    cudaGetSymbolAddress((void**)&h2a1partp,g_h2a1part);
    cudaGetSymbolAddress((void**)&sums4p,   g_sums4);
    cudaGetSymbolAddress((void**)&nexthp,   g_nexth);
    cudaGetSymbolAddress((void**)&scoresp,  g_scores);
    cudaGetSymbolAddress((void**)&logits2p, g_logits2);

    __half *ah,*w0hi,*w0lo,*w1hi,*w1lo,*h2awhi,*h2awlo,*h2a1whi,*h2a1wlo;
    __half *i2hhi,*i2hlo,*h2hhi,*h2hlo,*a2hhi,*a2hlo,*projhi,*projlo;
    __half *xh,*h01h,*xth,*nhh,*thh,*arh;
    cudaGetSymbolAddress((void**)&ah, g_att_h);
    cudaGetSymbolAddress((void**)&w0hi, g_w0_hi);      cudaGetSymbolAddress((void**)&w0lo, g_w0_lo);
    cudaGetSymbolAddress((void**)&w1hi, g_w1_hi);      cudaGetSymbolAddress((void**)&w1lo, g_w1_lo);
    cudaGetSymbolAddress((void**)&h2awhi, g_h2aw_hi);  cudaGetSymbolAddress((void**)&h2awlo, g_h2aw_lo);
    cudaGetSymbolAddress((void**)&h2a1whi, g_h2a1w_hi);cudaGetSymbolAddress((void**)&h2a1wlo, g_h2a1w_lo);
    cudaGetSymbolAddress((void**)&i2hhi, g_i2h_hi);    cudaGetSymbolAddress((void**)&i2hlo, g_i2h_lo);
    cudaGetSymbolAddress((void**)&h2hhi, g_h2h_hi);    cudaGetSymbolAddress((void**)&h2hlo, g_h2h_lo);
    cudaGetSymbolAddress((void**)&a2hhi, g_a2h_hi);    cudaGetSymbolAddress((void**)&a2hlo, g_a2h_lo);
    cudaGetSymbolAddress((void**)&projhi, g_proj_hi);  cudaGetSymbolAddress((void**)&projlo, g_proj_lo);
    cudaGetSymbolAddress((void**)&xh, g_x_h);
    cudaGetSymbolAddress((void**)&h01h, g_h01_h);
    cudaGetSymbolAddress((void**)&xth, g_xt_h);
    cudaGetSymbolAddress((void**)&nhh, g_nh_h);
    cudaGetSymbolAddress((void**)&thh, g_th_h);
    cudaGetSymbolAddress((void**)&arh, g_ar_h);

    const float* prev_c0 = inputs;
    const float* prev_h0 = inputs + 1*BR;
    const float* prev_c1 = inputs + 2*BR;
    const float* prev_h1 = inputs + 3*BR;

    float* sp0 = spart;
    float* sp1 = spart + (size_t)8*BA;

    cudaFuncSetAttribute(hmma_gemm_kernel, cudaFuncAttributeMaxDynamicSharedMemorySize, 2*STAGE_BYTES);
    cudaFuncSetAttribute(hgemm_kernel<1>, cudaFuncAttributeMaxDynamicSharedMemorySize, 2*HSTG);
    cudaFuncSetAttribute(hgemm_kernel<3>, cudaFuncAttributeMaxDynamicSharedMemorySize, 2*HSTG);

    // ---- converts ----
    {
        size_t n4 = (size_t)BB*AA*RR/4;
        tohalf_kernel<<<(unsigned)((n4+255)/256),256>>>(att, ah, n4);
        splith_kernel<<<256,256>>>(a2a_w,  w0hi, w0lo, AA*RR/4);
        splith_kernel<<<256,256>>>(a2a1_w, w1hi, w1lo, AA*RR/4);
        splith_kernel<<<256,256>>>(h2a_w,  h2awhi, h2awlo, AA*RR/4);
        splith_kernel<<<256,256>>>(h2a1_w, h2a1whi, h2a1wlo, AA*RR/4);
        splith_kernel<<<4096,256>>>(i2h_w, i2hhi, i2hlo, 2*LW/4);
        splith_kernel<<<4096,256>>>(h2h_w, h2hhi, h2hlo, 2*LW/4);
        splith_kernel<<<4096,256>>>(a2h_w, a2hhi, a2hlo, 2*LW/4);
        splith_kernel<<<5000,256>>>(proj_w, projhi, projlo, OUTN*RR/4);
        tohalf_kernel<<<64,256>>>(x, xh, BR/4);
        tohalf_kernel<<<64,256>>>(prev_h0, h01h, BR/4);
        tohalf_kernel<<<64,256>>>(prev_h1, h01h+BR, BR/4);
    }

    // ---- hh for both prev-attends: M=256, N=512, K=512, ksplit=4 ----
    hgemm_kernel<1><<<dim3(8,4,2),256,2*HSTG>>>(
        h01h, h2awhi, h2awlo, 0,0,0, 0,0,0, hhpartp, AA, 2*BA);
    reduce_bias_kernel<<<(2*BA+255)/256,256>>>(hhpartp, h2a_b, hhredp, 2*BA, 4, 2*BA);

    // ---- big tensor GEMMs ----
    hmma_gemm_kernel<<<dim3(8,512),256,2*STAGE_BYTES>>>(
        ah, w0hi, w0lo, w1hi, w1lo,
        a2a_b, a2a1_b, d2d_w, hhredp, hhredp+BA, v1hp, sp0, sp1);

    softmax512_kernel<<<BB,256>>>(sp0, w0p, 8);
    softmax512_kernel<<<BB,256>>>(sp1, w1p, 8);

    // both prev att_res (fp16 only)
    attres_kernel<true,false><<<dim3(2,BB),256>>>(att, w0p, w1p, nullptr, nullptr,
        nullptr, arh, arh+BR);

    // ---- layer 0 ----
    hgemm_kernel<3><<<dim3(64,4,1),256,2*HSTG>>>(
        xh, i2hhi, i2hlo,
        h01h, h2hhi, h2hlo,
        arh, a2hhi, a2hlo,
        sums4p, 4096, BB*4096);
    lstm_pw_kernel<<<BR/256,256>>>(sums4p, i2h_b, h2h_b, a2h_b, prev_c0,
                                   out + 0, nexthp, nhh);

    hgemm_kernel<1><<<dim3(8,4,1),256,2*HSTG>>>(
        nhh, h2a1whi, h2a1wlo, 0,0,0, 0,0,0, h2a1partp, AA, BA);
    v1_scores_kernel<<<dim3(AA,BB),128>>>(v1hp, h2a1partp, h2a1_b, d2d1_w, scoresp);
    softmax512_kernel<<<BB,256>>>(scoresp, w0p, 1);
    // top_h0 -> out+BR; xt = x + top_h0 -> fp16
    attres_kernel<false,true><<<dim3(2,BB),256>>>(att, w0p, nullptr, nexthp, x,
        out + BR, xth, nullptr);

    // ---- layer 1 ----
    hgemm_kernel<3><<<dim3(64,4,1),256,2*HSTG>>>(
        xth, i2hhi + LW, i2hlo + LW,
        h01h + BR, h2hhi + LW, h2hlo + LW,
        arh + BR, a2hhi + LW, a2hlo + LW,
        sums4p, 4096, BB*4096);
    lstm_pw_kernel<<<BR/256,256>>>(sums4p, i2h_b + LB, h2h_b + LB, a2h_b + LB, prev_c1,
                                   out + 2*BR, nexthp, nhh);

    hgemm_kernel<1><<<dim3(8,4,1),256,2*HSTG>>>(
        nhh, h2a1whi, h2a1wlo, 0,0,0, 0,0,0, h2a1partp, AA, BA);
    v1_scores_kernel<<<dim3(AA,BB),128>>>(v1hp, h2a1partp, h2a1_b, d2d1_w, scoresp);
    softmax512_kernel<<<BB,256>>>(scoresp, w0p, 1);
    // top_h1 -> out+3BR and fp16 for proj
    attres_kernel<false,true><<<dim3(2,BB),256>>>(att, w0p, nullptr, nexthp, nullptr,
        out + 3*BR, thh, nullptr);

    // ---- projection + log_softmax ----
    hgemm_kernel<1><<<dim3(157,2,1),256,2*HSTG>>>(
        thh, projhi, projlo, 0,0,0, 0,0,0, logits2p, OUTN, BB*OUTN);
    logsoftmax_kernel<<<BB,256>>>(logits2p, proj_b, out + 4*BR);
}

// round 6
// speedup vs baseline: 3.6860x; 1.2283x over previous
#include <cuda_runtime.h>
#include <cuda_fp16.h>
#include <math.h>
#include <cstdint>

#define BB 128
#define AA 512
#define RR 512
#define OUTN 10000
#define BR (BB*RR)
#define BA (BB*AA)
#define LW 2097152
#define LB 4096

// big HMMA GEMM tiling: 128x128, 1-term: stage = A 16K + W 16K
#define MT 128
#define NT 128
#define NSTAGES 8
#define STAGE_BYTES 32768

// ---------------- scratch (device globals; no allocations) ----------------
__device__ __half g_v1h[(size_t)BB*AA*AA];   // 67 MB, fp16 v1 (+bias)
__device__ float g_spart[2*8*BA];
__device__ float g_w0[BA];
__device__ float g_w1[BA];
__device__ float g_hhred[2*BA];
__device__ float g_hhpart[4*2*BA];
__device__ float g_h2a1part[4*BA];
__device__ float g_sums4[4*BB*4096];
__device__ float g_nexth[BR];
__device__ float g_scores[BA];
__device__ float g_logits2[(size_t)2*BB*OUTN];
// fp16 operands
__device__ __half g_att_h[(size_t)BB*AA*RR];
__device__ __half g_w0_h[AA*RR];
__device__ __half g_w1_h[AA*RR];
__device__ __half g_h2aw_h[AA*RR];
__device__ __half g_h2a1w_h[AA*RR];
__device__ __half g_i2h_h[2*LW];
__device__ __half g_h2h_h[2*LW];
__device__ __half g_a2h_h[2*LW];
__device__ __half g_proj_hi[OUTN*RR];
__device__ __half g_proj_lo[OUTN*RR];
__device__ __half g_x_h[BR];
__device__ __half g_h01_h[2*BR];
__device__ __half g_xt_h[BR];
__device__ __half g_nh_h[BR];
__device__ __half g_th_h[BR];
__device__ __half g_ar_h[2*BR];

// ---------------- PTX helpers ----------------
__device__ __forceinline__ uint32_t smem_u32(const void* p){
    uint32_t a;
    asm("{ .reg .u64 t; cvta.to.shared.u64 t, %1; cvt.u32.u64 %0, t; }" : "=r"(a) : "l"(p));
    return a;
}
__device__ __forceinline__ void cp16(uint32_t dst, const void* src){
    asm volatile("cp.async.cg.shared.global [%0], [%1], 16;\n" :: "r"(dst), "l"(src));
}
__device__ __forceinline__ void cp16z(uint32_t dst, const void* src, bool ok){
    int sz = ok ? 16 : 0;
    asm volatile("cp.async.cg.shared.global [%0], [%1], 16, %2;\n" :: "r"(dst), "l"(src), "r"(sz));
}
#define CP_COMMIT()  asm volatile("cp.async.commit_group;\n" ::: "memory")
#define CP_WAIT0()   asm volatile("cp.async.wait_group 0;\n" ::: "memory")
#define CP_WAIT1()   asm volatile("cp.async.wait_group 1;\n" ::: "memory")

#define SWZ(off) ((off) ^ (((off) >> 3) & 0x70))

__device__ __forceinline__ uint32_t lds_u32(uint32_t addr){
    uint32_t v; asm volatile("ld.shared.b32 %0, [%1];" : "=r"(v) : "r"(addr)); return v;
}
__device__ __forceinline__ void mma16816(float* c, const uint32_t* a, const uint32_t* b){
    asm volatile(
        "mma.sync.aligned.m16n8k16.row.col.f32.f16.f16.f32 "
        "{%0,%1,%2,%3}, {%4,%5,%6,%7}, {%8,%9}, {%0,%1,%2,%3};"
        : "+f"(c[0]), "+f"(c[1]), "+f"(c[2]), "+f"(c[3])
        : "r"(a[0]), "r"(a[1]), "r"(a[2]), "r"(a[3]), "r"(b[0]), "r"(b[1]));
}

// ---------------- fp32 -> fp16 single ----------------
__global__ void tohalf_kernel(const float* __restrict__ in, __half* __restrict__ out, size_t n4)
{
    size_t i = (size_t)blockIdx.x*blockDim.x + threadIdx.x;
    if (i >= n4) return;
    float4 x = ((const float4*)in)[i];
    __half h[4] = { __float2half_rn(x.x), __float2half_rn(x.y),
                    __float2half_rn(x.z), __float2half_rn(x.w) };
    ((uint2*)out)[i] = *(uint2*)h;
}
// ---------------- fp32 -> fp16 hi/lo split (proj only) ----------------
__global__ void splith_kernel(const float* __restrict__ in,
                              __half* __restrict__ hi, __half* __restrict__ lo, size_t n4)
{
    size_t i = (size_t)blockIdx.x*blockDim.x + threadIdx.x;
    if (i >= n4) return;
    float4 x = ((const float4*)in)[i];
    float xv[4] = {x.x, x.y, x.z, x.w};
    __half h[4], l[4];
    #pragma unroll
    for (int j=0;j<4;j++){
        h[j] = __float2half_rn(xv[j]);
        l[j] = __float2half_rn(xv[j] - __half2float(h[j]));
    }
    ((uint2*)hi)[i] = *(uint2*)h;
    ((uint2*)lo)[i] = *(uint2*)l;
}

// =====================================================================
// big HMMA fp16 1-term GEMM over att: C = att @ W^T
// grid.x = (nt4<<1)|set (8), grid.y = mtile (512)
// =====================================================================
__global__ __launch_bounds__(256, 1)
void hmma_gemm_kernel(const __half* __restrict__ Ah,
                      const __half* __restrict__ W0h, const __half* __restrict__ W1h,
                      const float* __restrict__ ba0, const float* __restrict__ ba1,
                      const float* __restrict__ wd0,
                      const float* __restrict__ hh0, const float* __restrict__ hh1,
                      __half* __restrict__ v1out,
                      float* __restrict__ sp0, float* __restrict__ sp1)
{
    extern __shared__ char dsm[];
    const int tid  = threadIdx.x;
    const int wid  = tid >> 5;
    const int lane = tid & 31;
    const int grp  = lane >> 2;
    const int tid4 = lane & 3;
    const int set  = blockIdx.x & 1;
    const int nt4  = blockIdx.x >> 1;
    const int mBase = blockIdx.y * MT;
    const int nBase4 = nt4 * NT;
    const int wm = wid >> 1;
    const int wn = wid & 1;

    const __half* Wh = set ? W1h : W0h;
    const float* bias = set ? ba1 : ba0;

    const uint32_t sbase = smem_u32(dsm);

    float acc[2][8][4];
    #pragma unroll
    for (int mt=0;mt<2;mt++)
        #pragma unroll
        for (int nt=0;nt<8;nt++)
            #pragma unroll
            for (int q=0;q<4;q++) acc[mt][nt][q]=0.f;

    auto load_stage = [&](int s){
        const uint32_t base = sbase + (s & 1) * STAGE_BYTES;
        const int kOff = s * 64;
        #pragma unroll
        for (int i = 0; i < 4; i++){              // A: 1024 chunks
            int idx = tid + i * 256;
            int r = idx >> 3;
            int ch = idx & 7;
            const __half* src = Ah + (size_t)(mBase + r) * RR + kOff + ch * 8;
            cp16(base + SWZ(r * 128 + ch * 16), src);
        }
        #pragma unroll
        for (int i = 0; i < 4; i++){              // B: 1024 chunks
            int idx = tid + i * 256;
            int r = idx >> 3;
            int ch = idx & 7;
            const __half* src = Wh + (size_t)(nBase4 + r) * RR + kOff + ch * 8;
            cp16(base + 16384 + SWZ(r * 128 + ch * 16), src);
        }
        CP_COMMIT();
    };

    load_stage(0);

    for (int s = 0; s < NSTAGES; s++){
        if (s + 1 < NSTAGES){ load_stage(s + 1); CP_WAIT1(); }
        else                 { CP_WAIT0(); }
        __syncthreads();

        const uint32_t sA = sbase + (s & 1) * STAGE_BYTES;
        const uint32_t sB = sA + 16384;
        #pragma unroll
        for (int k16 = 0; k16 < 4; k16++){
            const int kc = k16 * 32 + tid4 * 4;
            uint32_t aH[2][4];
            #pragma unroll
            for (int mt = 0; mt < 2; mt++){
                int r0 = (wm*32 + mt*16 + grp) * 128 + kc;
                int r1 = r0 + 8*128;
                aH[mt][0] = lds_u32(sA + SWZ(r0));
                aH[mt][1] = lds_u32(sA + SWZ(r1));
                aH[mt][2] = lds_u32(sA + SWZ(r0 + 16));
                aH[mt][3] = lds_u32(sA + SWZ(r1 + 16));
            }
            #pragma unroll
            for (int nt = 0; nt < 8; nt++){
                int rb = (wn*64 + nt*8 + grp) * 128 + kc;
                uint32_t bH[2];
                bH[0] = lds_u32(sB + SWZ(rb));
                bH[1] = lds_u32(sB + SWZ(rb + 16));
                #pragma unroll
                for (int mt = 0; mt < 2; mt++)
                    mma16816(acc[mt][nt], aH[mt], bH);
            }
        }
        __syncthreads();
    }

    if (set == 1){
        #pragma unroll
        for (int mt = 0; mt < 2; mt++){
            #pragma unroll
            for (int rh = 0; rh < 2; rh++){
                int m = mBase + wm*32 + mt*16 + rh*8 + grp;
                __half* dst = v1out + (size_t)m * AA;
                #pragma unroll
                for (int nt = 0; nt < 8; nt++){
                    int n0 = nBase4 + wn*64 + nt*8 + tid4*2;
                    __half2 h2 = __floats2half2_rn(acc[mt][nt][rh*2+0] + bias[n0],
                                                   acc[mt][nt][rh*2+1] + bias[n0+1]);
                    *(__half2*)(dst + n0) = h2;
                }
            }
        }
    } else {
        const int part = nt4*2 + wn;
        #pragma unroll
        for (int mt = 0; mt < 2; mt++){
            #pragma unroll
            for (int rh = 0; rh < 2; rh++){
                int m = mBase + wm*32 + mt*16 + rh*8 + grp;
                float h0 = hh0[m], h1 = hh1[m];
                float p0 = 0.f, p1 = 0.f;
                #pragma unroll
                for (int nt = 0; nt < 8; nt++){
                    int n0 = nBase4 + wn*64 + nt*8 + tid4*2;
                    float v0 = acc[mt][nt][rh*2+0] + bias[n0];
                    float v1v = acc[mt][nt][rh*2+1] + bias[n0+1];
                    float wv0 = wd0[n0], wv1 = wd0[n0+1];
                    p0 += tanhf(v0 + h0)*wv0 + tanhf(v1v + h0)*wv1;
                    p1 += tanhf(v0 + h1)*wv0 + tanhf(v1v + h1)*wv1;
                }
                p0 += __shfl_down_sync(0xffffffffu, p0, 2, 4);
                p0 += __shfl_down_sync(0xffffffffu, p0, 1, 4);
                p1 += __shfl_down_sync(0xffffffffu, p1, 2, 4);
                p1 += __shfl_down_sync(0xffffffffu, p1, 1, 4);
                if (tid4 == 0){
                    sp0[(size_t)part*BA + m] = p0;
                    sp1[(size_t)part*BA + m] = p1;
                }
            }
        }
    }
}

// =====================================================================
// Generic fp16 GEMM, 128x64 tile, multi-source K, K-split, 1- or 2-term W.
// =====================================================================
template<int NSRC, bool TWOTERM>
__global__ __launch_bounds__(256, 1)
void hgemm_kernel(const __half* __restrict__ Xh0,
                  const __half* __restrict__ Whi0, const __half* __restrict__ Wlo0,
                  const __half* __restrict__ Xh1,
                  const __half* __restrict__ Whi1, const __half* __restrict__ Wlo1,
                  const __half* __restrict__ Xh2,
                  const __half* __restrict__ Whi2, const __half* __restrict__ Wlo2,
                  float* __restrict__ out, int Nreal, int kStride)
{
    constexpr uint32_t STG = TWOTERM ? 32768 : 24576;
    extern __shared__ char dsm[];
    const int tid  = threadIdx.x;
    const int wid  = tid >> 5;
    const int lane = tid & 31;
    const int grp  = lane >> 2;
    const int tid4 = lane & 3;
    const int nBase = blockIdx.x * 64;
    const int kIdx  = blockIdx.y;
    const int mBase = blockIdx.z * 128;
    const int wm = wid >> 1;
    const int wn = wid & 1;
    const uint32_t sbase = smem_u32(dsm);

    const int spc  = (NSRC * 8) / gridDim.y;
    const int sBeg = kIdx * spc;

    float acc[2][4][4];
    #pragma unroll
    for (int mt=0;mt<2;mt++)
        #pragma unroll
        for (int nt=0;nt<4;nt++)
            #pragma unroll
            for (int q=0;q<4;q++) acc[mt][nt][q]=0.f;

    auto load_stage = [&](int s, int buf){
        const uint32_t base = sbase + buf * STG;
        const int src = s >> 3;
        const int kOff = (s & 7) * 64;
        const __half *xh, *wh, *wl;
        if (NSRC == 1 || src == 0){ xh=Xh0; wh=Whi0; wl=Wlo0; }
        else if (src == 1){ xh=Xh1; wh=Whi1; wl=Wlo1; }
        else { xh=Xh2; wh=Whi2; wl=Wlo2; }
        #pragma unroll
        for (int i = 0; i < 4; i++){              // A: 1024 chunks
            int idx = tid + i * 256;
            int r = idx >> 3;
            int ch = idx & 7;
            const __half* src_p = xh + (size_t)(mBase + r) * 512 + kOff + ch * 8;
            cp16(base + SWZ(r * 128 + ch * 16), src_p);
        }
        #pragma unroll
        for (int i = 0; i < (TWOTERM ? 4 : 2); i++){  // B chunks
            int idx = tid + i * 256;
            int half = idx >> 9;
            int r = (idx >> 3) & 63;
            int ch = idx & 7;
            bool ok = (nBase + r) < Nreal;
            const __half* src_p = ((TWOTERM && half) ? wl : wh) + (size_t)(nBase + r) * 512 + kOff + ch * 8;
            cp16z(base + 16384 + half * 8192 + SWZ(r * 128 + ch * 16), src_p, ok);
        }
        CP_COMMIT();
    };

    load_stage(sBeg, 0);

    for (int i = 0; i < spc; i++){
        if (i + 1 < spc){ load_stage(sBeg + i + 1, (i + 1) & 1); CP_WAIT1(); }
        else            { CP_WAIT0(); }
        __syncthreads();

        const uint32_t sA  = sbase + (i & 1) * STG;
        const uint32_t sBh = sA + 16384;
        const uint32_t sBl = sA + 24576;
        #pragma unroll
        for (int k16 = 0; k16 < 4; k16++){
            const int kc = k16 * 32 + tid4 * 4;
            uint32_t aH[2][4];
            #pragma unroll
            for (int mt = 0; mt < 2; mt++){
                int r0 = (wm*32 + mt*16 + grp) * 128 + kc;
                int r1 = r0 + 8*128;
                aH[mt][0] = lds_u32(sA + SWZ(r0));
                aH[mt][1] = lds_u32(sA + SWZ(r1));
                aH[mt][2] = lds_u32(sA + SWZ(r0 + 16));
                aH[mt][3] = lds_u32(sA + SWZ(r1 + 16));
            }
            #pragma unroll
            for (int nt = 0; nt < 4; nt++){
                int rb = (wn*32 + nt*8 + grp) * 128 + kc;
                uint32_t bH[2];
                bH[0] = lds_u32(sBh + SWZ(rb));
                bH[1] = lds_u32(sBh + SWZ(rb + 16));
                #pragma unroll
                for (int mt = 0; mt < 2; mt++)
                    mma16816(acc[mt][nt], aH[mt], bH);
                if (TWOTERM){
                    uint32_t bL[2];
                    bL[0] = lds_u32(sBl + SWZ(rb));
                    bL[1] = lds_u32(sBl + SWZ(rb + 16));
                    #pragma unroll
                    for (int mt = 0; mt < 2; mt++)
                        mma16816(acc[mt][nt], aH[mt], bL);
                }
            }
        }
        __syncthreads();
    }

    float* obase = out + (size_t)kIdx * kStride;
    #pragma unroll
    for (int mt = 0; mt < 2; mt++){
        #pragma unroll
        for (int rh = 0; rh < 2; rh++){
            int m = mBase + wm*32 + mt*16 + rh*8 + grp;
            #pragma unroll
            for (int nt = 0; nt < 4; nt++){
                int n0 = nBase + wn*32 + nt*8 + tid4*2;
                if (n0 < Nreal){
                    float2 v2;
                    v2.x = acc[mt][nt][rh*2+0];
                    v2.y = acc[mt][nt][rh*2+1];
                    *(float2*)(obase + (size_t)m * Nreal + n0) = v2;
                }
            }
        }
    }
}

// ---------------- reduce partials + bias (biasN=512) ----------------
__global__ void reduce_bias_kernel(const float* __restrict__ in, const float* __restrict__ bias,
                                   float* __restrict__ out, int n, int parts, int pstride)
{
    int i = blockIdx.x*256 + threadIdx.x;
    if (i >= n) return;
    float s = bias[i & 511];
    for (int p = 0; p < parts; p++) s += in[(size_t)p*pstride + i];
    out[i] = s;
}

// ---------------- softmax over a (A=512), summing nparts partials ----------------
__global__ void softmax512_kernel(const float* __restrict__ in, float* __restrict__ out, int nparts)
{
    __shared__ float sm[8];
    int b = blockIdx.x, t = threadIdx.x;
    float v0=0.f, v1=0.f;
    for (int p=0;p<nparts;p++){
        const float* ip = in + (size_t)p*BA + (size_t)b*AA;
        v0 += ip[t]; v1 += ip[t+256];
    }
    float m = fmaxf(v0,v1);
    for (int o=16;o;o>>=1) m = fmaxf(m, __shfl_xor_sync(0xffffffffu,m,o));
    if ((t&31)==0) sm[t>>5]=m;
    __syncthreads();
    float M = sm[0];
    #pragma unroll
    for (int i=1;i<8;i++) M = fmaxf(M, sm[i]);
    __syncthreads();
    float e0=expf(v0-M), e1=expf(v1-M);
    float s = e0+e1;
    for (int o=16;o;o>>=1) s += __shfl_xor_sync(0xffffffffu,s,o);
    if ((t&31)==0) sm[t>>5]=s;
    __syncthreads();
    float S=0.f;
    #pragma unroll
    for (int i=0;i<8;i++) S += sm[i];
    float inv = 1.f/S;
    out[(size_t)b*AA + t]     = e0*inv;
    out[(size_t)b*AA + t+256] = e1*inv;
}

// ---------------- score scan over fp16 v1, fusing h2a1 partial-reduce ----------------
__global__ void v1_scores_kernel(const __half* __restrict__ v1, const float* __restrict__ parts,
                                 const float* __restrict__ hbias,
                                 const float* __restrict__ wd, float* __restrict__ scores)
{
    __shared__ float sm[4];
    int a = blockIdx.x, b = blockIdx.y, t = threadIdx.x;   // 128 threads
    size_t hidx = (size_t)b*AA + a;
    float h = hbias[a];
    #pragma unroll
    for (int p=0;p<4;p++) h += parts[(size_t)p*BA + hidx];
    uint2 u = ((const uint2*)(v1 + hidx*AA))[t];
    float2 f01 = __half22float2(*reinterpret_cast<__half2*>(&u.x));
    float2 f23 = __half22float2(*reinterpret_cast<__half2*>(&u.y));
    float4 w = ((const float4*)wd)[t];
    float s = tanhf(f01.x+h)*w.x + tanhf(f01.y+h)*w.y + tanhf(f23.x+h)*w.z + tanhf(f23.y+h)*w.w;
    for (int o=16;o;o>>=1) s += __shfl_xor_sync(0xffffffffu,s,o);
    if ((t&31)==0) sm[t>>5]=s;
    __syncthreads();
    if (t==0) scores[hidx] = sm[0]+sm[1]+sm[2]+sm[3];
}

// ---------------- att_res over fp16 att (+ fused fp16 converts) ----------------
template<bool DUAL, bool ADD>
__global__ void attres_kernel(const __half* __restrict__ att,
                              const float* __restrict__ w0, const float* __restrict__ w1,
                              const float* __restrict__ addv, const float* __restrict__ xadd,
                              float* __restrict__ out0,
                              __half* __restrict__ h0out, __half* __restrict__ h1out)
{
    __shared__ float sw0[AA];
    __shared__ float sw1[AA];
    int b = blockIdx.y;
    int r = blockIdx.x*256 + threadIdx.x;
    for (int a=threadIdx.x; a<AA; a+=256){
        sw0[a]=w0[(size_t)b*AA+a];
        if (DUAL) sw1[a]=w1[(size_t)b*AA+a];
    }
    __syncthreads();
    float acc0=0.f, acc1=0.f;
    const __half* ap = att + (size_t)b*AA*RR + r;
    #pragma unroll 8
    for (int a=0;a<AA;a++){
        float av = __half2float(ap[(size_t)a*RR]);
        acc0 = fmaf(sw0[a], av, acc0);
        if (DUAL) acc1 = fmaf(sw1[a], av, acc1);
    }
    size_t idx = (size_t)b*RR + r;
    if (ADD) acc0 += addv[idx];
    if (out0) out0[idx] = acc0;
    float e0 = xadd ? acc0 + xadd[idx] : acc0;
    h0out[idx] = __float2half_rn(e0);
    if (DUAL) h1out[idx] = __float2half_rn(acc1);
}

// ---------------- LSTM pointwise: sums 4 K-split partials + biases ----------------
__global__ void lstm_pw_kernel(const float* __restrict__ sums4,
                               const float* __restrict__ bi, const float* __restrict__ bh,
                               const float* __restrict__ ba,
                               const float* __restrict__ prev_c,
                               float* __restrict__ next_c, float* __restrict__ next_h,
                               __half* __restrict__ nh_h)
{
    int idx = blockIdx.x*256 + threadIdx.x;
    int b = idx >> 9, r = idx & 511;
    float pc = prev_c[idx];
    float cs=0.f, hs=0.f;
    #pragma unroll
    for (int p=0;p<2;p++){
        float g[4];
        #pragma unroll
        for (int gi=0; gi<4; gi++){
            int off = p*2048 + gi*512 + r;
            float s = bi[off] + bh[off] + ba[off];
            #pragma unroll
            for (int q=0;q<4;q++) s += sums4[(size_t)q*(BB*4096) + (size_t)b*4096 + off];
            g[gi] = s;
        }
        float ig = 1.f/(1.f+expf(-g[0]));
        float fg = 1.f/(1.f+expf(-g[1]));
        float og = 1.f/(1.f+expf(-g[2]));
        float tt = tanhf(g[3]);
        float c  = fg*pc + ig*tt;
        cs += c; hs += og*tanhf(c);
    }
    float nc = cs*0.5f, nh = hs*0.5f;
    next_c[idx] = nc;
    next_h[idx] = nh;
    nh_h[idx] = __float2half_rn(nh);
}

// ---------------- log_softmax: sums 2 proj partials + bias, smem-cached ----------------
__global__ void logsoftmax_kernel(const float* __restrict__ parts, const float* __restrict__ bias,
                                  float* __restrict__ out)
{
    __shared__ float sx[OUTN];
    __shared__ float sm[8];
    int b = blockIdx.x, t = threadIdx.x;
    const float* a0 = parts + (size_t)b*OUTN;
    const float* a1 = parts + (size_t)(BB + b)*OUTN;
    for (int i=t;i<OUTN;i+=256) sx[i] = a0[i] + a1[i] + bias[i];
    __syncthreads();
    float m = -3.4e38f;
    for (int i=t;i<OUTN;i+=256) m = fmaxf(m, sx[i]);
    for (int o=16;o;o>>=1) m = fmaxf(m, __shfl_xor_sync(0xffffffffu,m,o));
    if ((t&31)==0) sm[t>>5]=m;
    __syncthreads();
    float M = sm[0];
    #pragma unroll
    for (int i=1;i<8;i++) M = fmaxf(M, sm[i]);
    __syncthreads();
    float s=0.f;
    for (int i=t;i<OUTN;i+=256) s += expf(sx[i]-M);
    for (int o=16;o;o>>=1) s += __shfl_xor_sync(0xffffffffu,s,o);
    if ((t&31)==0) sm[t>>5]=s;
    __syncthreads();
    float S=0.f;
    #pragma unroll
    for (int i=0;i<8;i++) S += sm[i];
    float L = M + logf(S);
    for (int i=t;i<OUTN;i+=256) out[(size_t)b*OUTN+i] = sx[i]-L;
}

// =====================================================================
extern "C" void kernel_launch(void* const* d_in, const int* in_sizes, int n_in,
                              void* d_out, int out_size)
{
    const float* x      = (const float*)d_in[0];
    const float* att    = (const float*)d_in[1];
    const float* inputs = (const float*)d_in[2];
    const float* a2a_w  = (const float*)d_in[3];
    const float* a2a_b  = (const float*)d_in[4];
    const float* h2a_w  = (const float*)d_in[5];
    const float* h2a_b  = (const float*)d_in[6];
    const float* d2d_w  = (const float*)d_in[7];
    const float* a2a1_w = (const float*)d_in[9];
    const float* a2a1_b = (const float*)d_in[10];
    const float* h2a1_w = (const float*)d_in[11];
    const float* h2a1_b = (const float*)d_in[12];
    const float* d2d1_w = (const float*)d_in[13];
    const float* i2h_w  = (const float*)d_in[15];
    const float* i2h_b  = (const float*)d_in[16];
    const float* h2h_w  = (const float*)d_in[17];
    const float* h2h_b  = (const float*)d_in[18];
    const float* a2h_w  = (const float*)d_in[19];
    const float* a2h_b  = (const float*)d_in[20];
    const float* proj_w = (const float*)d_in[21];
    const float* proj_b = (const float*)d_in[22];
    float* out = (float*)d_out;

    float *spart, *w0p, *w1p, *hhredp, *hhpartp, *h2a1partp, *sums4p, *nexthp, *scoresp, *logits2p;
    __half* v1hp;
    cudaGetSymbolAddress((void**)&v1hp,     g_v1h);
    cudaGetSymbolAddress((void**)&spart,    g_spart);
    cudaGetSymbolAddress((void**)&w0p,      g_w0);
    cudaGetSymbolAddress((void**)&w1p,      g_w1);
    cudaGetSymbolAddress((void**)&hhredp,   g_hhred);
    cudaGetSymbolAddress((void**)&hhpartp,  g_hhpart);
    cudaGetSymbolAddress((void**)&h2a1partp,g_h2a1part);
    cudaGetSymbolAddress((void**)&sums4p,   g_sums4);
    cudaGetSymbolAddress((void**)&nexthp,   g_nexth);
    cudaGetSymbolAddress((void**)&scoresp,  g_scores);
    cudaGetSymbolAddress((void**)&logits2p, g_logits2);

    __half *ah,*w0h,*w1h,*h2awh,*h2a1wh,*i2hh,*h2hh,*a2hh,*projhi,*projlo;
    __half *xh,*h01h,*xth,*nhh,*thh,*arh;
    cudaGetSymbolAddress((void**)&ah, g_att_h);
    cudaGetSymbolAddress((void**)&w0h, g_w0_h);
    cudaGetSymbolAddress((void**)&w1h, g_w1_h);
    cudaGetSymbolAddress((void**)&h2awh, g_h2aw_h);
    cudaGetSymbolAddress((void**)&h2a1wh, g_h2a1w_h);
    cudaGetSymbolAddress((void**)&i2hh, g_i2h_h);
    cudaGetSymbolAddress((void**)&h2hh, g_h2h_h);
    cudaGetSymbolAddress((void**)&a2hh, g_a2h_h);
    cudaGetSymbolAddress((void**)&projhi, g_proj_hi);
    cudaGetSymbolAddress((void**)&projlo, g_proj_lo);
    cudaGetSymbolAddress((void**)&xh, g_x_h);
    cudaGetSymbolAddress((void**)&h01h, g_h01_h);
    cudaGetSymbolAddress((void**)&xth, g_xt_h);
    cudaGetSymbolAddress((void**)&nhh, g_nh_h);
    cudaGetSymbolAddress((void**)&thh, g_th_h);
    cudaGetSymbolAddress((void**)&arh, g_ar_h);

    const float* prev_c0 = inputs;
    const float* prev_h0 = inputs + 1*BR;
    const float* prev_c1 = inputs + 2*BR;
    const float* prev_h1 = inputs + 3*BR;

    float* sp0 = spart;
    float* sp1 = spart + (size_t)8*BA;

    cudaFuncSetAttribute(hmma_gemm_kernel, cudaFuncAttributeMaxDynamicSharedMemorySize, 2*STAGE_BYTES);
    cudaFuncSetAttribute((hgemm_kernel<1,false>), cudaFuncAttributeMaxDynamicSharedMemorySize, 2*24576);
    cudaFuncSetAttribute((hgemm_kernel<3,false>), cudaFuncAttributeMaxDynamicSharedMemorySize, 2*24576);
    cudaFuncSetAttribute((hgemm_kernel<1,true>),  cudaFuncAttributeMaxDynamicSharedMemorySize, 2*32768);

    // ---- converts ----
    {
        size_t n4 = (size_t)BB*AA*RR/4;
        tohalf_kernel<<<(unsigned)((n4+255)/256),256>>>(att, ah, n4);
        tohalf_kernel<<<256,256>>>(a2a_w,  w0h, AA*RR/4);
        tohalf_kernel<<<256,256>>>(a2a1_w, w1h, AA*RR/4);
        tohalf_kernel<<<256,256>>>(h2a_w,  h2awh, AA*RR/4);
        tohalf_kernel<<<256,256>>>(h2a1_w, h2a1wh, AA*RR/4);
        tohalf_kernel<<<4096,256>>>(i2h_w, i2hh, 2*LW/4);
        tohalf_kernel<<<4096,256>>>(h2h_w, h2hh, 2*LW/4);
        tohalf_kernel<<<4096,256>>>(a2h_w, a2hh, 2*LW/4);
        splith_kernel<<<5000,256>>>(proj_w, projhi, projlo, OUTN*RR/4);
        tohalf_kernel<<<64,256>>>(x, xh, BR/4);
        tohalf_kernel<<<64,256>>>(prev_h0, h01h, BR/4);
        tohalf_kernel<<<64,256>>>(prev_h1, h01h+BR, BR/4);
    }

    // ---- hh for both prev-attends: M=256, N=512, K=512, ksplit=4 ----
    hgemm_kernel<1,false><<<dim3(8,4,2),256,2*24576>>>(
        h01h, h2awh, 0, 0,0,0, 0,0,0, hhpartp, AA, 2*BA);
    reduce_bias_kernel<<<(2*BA+255)/256,256>>>(hhpartp, h2a_b, hhredp, 2*BA, 4, 2*BA);

    // ---- big tensor GEMMs ----
    hmma_gemm_kernel<<<dim3(8,512),256,2*STAGE_BYTES>>>(
        ah, w0h, w1h, a2a_b, a2a1_b, d2d_w, hhredp, hhredp+BA, v1hp, sp0, sp1);

    softmax512_kernel<<<BB,256>>>(sp0, w0p, 8);
    softmax512_kernel<<<BB,256>>>(sp1, w1p, 8);

    // both prev att_res (fp16 att source)
    attres_kernel<true,false><<<dim3(2,BB),256>>>(ah, w0p, w1p, nullptr, nullptr,
        nullptr, arh, arh+BR);

    // ---- layer 0 ----
    hgemm_kernel<3,false><<<dim3(64,4,1),256,2*24576>>>(
        xh, i2hh, 0,
        h01h, h2hh, 0,
        arh, a2hh, 0,
        sums4p, 4096, BB*4096);
    lstm_pw_kernel<<<BR/256,256>>>(sums4p, i2h_b, h2h_b, a2h_b, prev_c0,
                                   out + 0, nexthp, nhh);

    hgemm_kernel<1,false><<<dim3(8,4,1),256,2*24576>>>(
        nhh, h2a1wh, 0, 0,0,0, 0,0,0, h2a1partp, AA, BA);
    v1_scores_kernel<<<dim3(AA,BB),128>>>(v1hp, h2a1partp, h2a1_b, d2d1_w, scoresp);
    softmax512_kernel<<<BB,256>>>(scoresp, w0p, 1);
    // top_h0 -> out+BR; xt = x + top_h0 -> fp16
    attres_kernel<false,true><<<dim3(2,BB),256>>>(ah, w0p, nullptr, nexthp, x,
        out + BR, xth, nullptr);

    // ---- layer 1 ----
    hgemm_kernel<3,false><<<dim3(64,4,1),256,2*24576>>>(
        xth, i2hh + LW, 0,
        h01h + BR, h2hh + LW, 0,
        arh + BR, a2hh + LW, 0,
        sums4p, 4096, BB*4096);
    lstm_pw_kernel<<<BR/256,256>>>(sums4p, i2h_b + LB, h2h_b + LB, a2h_b + LB, prev_c1,
                                   out + 2*BR, nexthp, nhh);

    hgemm_kernel<1,false><<<dim3(8,4,1),256,2*24576>>>(
        nhh, h2a1wh, 0, 0,0,0, 0,0,0, h2a1partp, AA, BA);
    v1_scores_kernel<<<dim3(AA,BB),128>>>(v1hp, h2a1partp, h2a1_b, d2d1_w, scoresp);
    softmax512_kernel<<<BB,256>>>(scoresp, w0p, 1);
    // top_h1 -> out+3BR and fp16 for proj
    attres_kernel<false,true><<<dim3(2,BB),256>>>(ah, w0p, nullptr, nexthp, nullptr,
        out + 3*BR, thh, nullptr);

    // ---- projection + log_softmax (2-term: logits are output-critical) ----
    hgemm_kernel<1,true><<<dim3(157,2,1),256,2*32768>>>(
        thh, projhi, projlo, 0,0,0, 0,0,0, logits2p, OUTN, BB*OUTN);
    logsoftmax_kernel<<<BB,256>>>(logits2p, proj_b, out + 4*BR);
}